// round 1
// baseline (speedup 1.0000x reference)
#include <cuda_runtime.h>
#include <cuda_bf16.h>

// Problem constants (fixed shapes per reference)
#define BATCH    4
#define N_PER    300
#define IN_DIM   256
#define KEY_DIM  32
#define HW       25600          // 160*160
#define PIX_BLOCKS 200          // 25600 / 128 pixels per block
#define THREADS  128

typedef unsigned long long ull;

__device__ __forceinline__ ull pack2(float lo, float hi) {
    ull r; asm("mov.b64 %0, {%1,%2};" : "=l"(r) : "f"(lo), "f"(hi)); return r;
}
__device__ __forceinline__ void unpack2(ull v, float& lo, float& hi) {
    asm("mov.b64 {%0,%1}, %2;" : "=f"(lo), "=f"(hi) : "l"(v));
}
__device__ __forceinline__ ull fma2(ull a, ull b, ull c) {
    ull d; asm("fma.rn.f32x2 %0, %1, %2, %3;" : "=l"(d) : "l"(a), "l"(b), "l"(c)); return d;
}
__device__ __forceinline__ ull add2(ull a, ull b) {
    ull d; asm("add.rn.f32x2 %0, %1, %2;" : "=l"(d) : "l"(a), "l"(b)); return d;
}

// q projection result: [1200][32]
__device__ float g_q[BATCH * N_PER * KEY_DIM];

// ---------------------------------------------------------------------------
// Kernel 1: q = in_feats @ qry_w^T + qry_b    (tiny: 1200x32x256)
// One warp per row; lane = output channel o.
// ---------------------------------------------------------------------------
__global__ void qproj_kernel(const float* __restrict__ in_feats,
                             const float* __restrict__ qry_w,
                             const float* __restrict__ qry_b) {
    int warp = threadIdx.x >> 5;
    int lane = threadIdx.x & 31;
    int row  = blockIdx.x * 8 + warp;           // grid=150, 8 warps/block -> 1200 rows

    const float4* inf4 = (const float4*)(in_feats + (size_t)row * IN_DIM);
    const float4* qw4  = (const float4*)(qry_w    + (size_t)lane * IN_DIM);

    float a0 = 0.f, a1 = 0.f;
#pragma unroll 8
    for (int i = 0; i < IN_DIM / 4; i++) {
        float4 x = inf4[i];
        float4 w = qw4[i];
        a0 = fmaf(x.x, w.x, a0);
        a1 = fmaf(x.y, w.y, a1);
        a0 = fmaf(x.z, w.z, a0);
        a1 = fmaf(x.w, w.w, a1);
    }
    g_q[row * KEY_DIM + lane] = a0 + a1 + qry_b[lane];
}

// ---------------------------------------------------------------------------
// Kernel 2 (fused): per pixel p of batch b:
//   key[o] = sum_c key_w[o,c] * feat[b,c,p] + key_b[o]     (32 f32x2 accs, c-pair lanes)
//   out[b,n,p] = sum_o q[b,n,o] * key[o]                   (o-pair lanes, q from smem)
// Grid: 800 blocks (4 batches x 200 pixel tiles), 128 threads, 1 pixel/thread.
// ---------------------------------------------------------------------------
__global__ __launch_bounds__(THREADS, 3)
void seg_kernel(const float* __restrict__ feat_map,
                const float* __restrict__ key_w,
                const float* __restrict__ key_b,
                float* __restrict__ out) {
    extern __shared__ char smem_raw[];
    float* kw_s = (float*)smem_raw;                 // 32*256 f32 = 32768 B
    float* q_s  = (float*)(smem_raw + 32768);       // 300*32 f32 = 38400 B

    const int tid = threadIdx.x;
    const int b   = blockIdx.x / PIX_BLOCKS;
    const int p   = (blockIdx.x % PIX_BLOCKS) * THREADS + tid;

    // Stage key_w [o][c] (c contiguous -> natural c-pair packing) and q[b]
    {
        const float4* src = (const float4*)key_w;
        float4* dst = (float4*)kw_s;
        for (int i = tid; i < (KEY_DIM * IN_DIM) / 4; i += THREADS) dst[i] = src[i];
        const float4* qsrc = (const float4*)(g_q + (size_t)b * N_PER * KEY_DIM);
        float4* qdst = (float4*)q_s;
        for (int i = tid; i < (N_PER * KEY_DIM) / 4; i += THREADS) qdst[i] = qsrc[i];
    }
    __syncthreads();

    const float* fm = feat_map + (size_t)b * IN_DIM * HW + p;

    // key accumulators: acc[o] lanes = {sum over even c, sum over odd c}
    // bias folded in via init {key_b[o], 0}
    ull acc[KEY_DIM];
#pragma unroll
    for (int o = 0; o < KEY_DIM; o++) acc[o] = pack2(key_b[o], 0.f);

    const ulonglong2* kwv = (const ulonglong2*)kw_s; // [o][cq] of {w[c],w[c+1]},{w[c+2],w[c+3]}

    // -------- Stage 1: 64 channel-quads, software-pipelined feat loads --------
    float f0 = fm[0], f1 = fm[HW], f2 = fm[2 * HW], f3 = fm[3 * HW];
    for (int cq = 0; cq < 64; cq++) {
        ull fd01 = pack2(f0, f1);
        ull fd23 = pack2(f2, f3);

        int c4 = 4 * cq + 4;
        if (c4 > 252) c4 = 252;                       // branchless tail (redundant reload)
        float nf0 = fm[(size_t)c4 * HW];
        float nf1 = fm[(size_t)(c4 + 1) * HW];
        float nf2 = fm[(size_t)(c4 + 2) * HW];
        float nf3 = fm[(size_t)(c4 + 3) * HW];

#pragma unroll
        for (int o = 0; o < KEY_DIM; o++) {
            ulonglong2 w = kwv[o * 64 + cq];          // broadcast LDS.128, conflict-free
            acc[o] = fma2(fd01, w.x, acc[o]);
            acc[o] = fma2(fd23, w.y, acc[o]);
        }
        f0 = nf0; f1 = nf1; f2 = nf2; f3 = nf3;
    }

    // -------- Repack: kp[k] = {key[2k], key[2k+1]} (horizontal sums) --------
    ull kp[KEY_DIM / 2];
#pragma unroll
    for (int k = 0; k < KEY_DIM / 2; k++) {
        float ax, ay, bx, by;
        unpack2(acc[2 * k], ax, ay);
        unpack2(acc[2 * k + 1], bx, by);
        kp[k] = pack2(ax + ay, bx + by);
    }

    // -------- Stage 2: out[n] = sum_o q[n,o]*key[o], 300 outputs --------
    const ulonglong2* qv = (const ulonglong2*)q_s;    // 8 x ulonglong2 per n (32 floats)
    float* optr = out + (size_t)b * N_PER * HW + p;

    for (int n = 0; n < N_PER; n++) {
        const ulonglong2* qn = qv + n * 8;
        ull s0 = 0ull, s1 = 0ull, s2 = 0ull, s3 = 0ull; // 0ull == {+0.f,+0.f}
#pragma unroll
        for (int j = 0; j < 8; j++) {
            ulonglong2 qq = qn[j];                    // broadcast LDS.128
            if ((j & 1) == 0) {
                s0 = fma2(kp[2 * j],     qq.x, s0);
                s1 = fma2(kp[2 * j + 1], qq.y, s1);
            } else {
                s2 = fma2(kp[2 * j],     qq.x, s2);
                s3 = fma2(kp[2 * j + 1], qq.y, s3);
            }
        }
        ull t = add2(add2(s0, s1), add2(s2, s3));
        float tx, ty;
        unpack2(t, tx, ty);
        optr[0] = tx + ty;                            // coalesced: threads -> consecutive p
        optr += HW;
    }
}

// ---------------------------------------------------------------------------
extern "C" void kernel_launch(void* const* d_in, const int* in_sizes, int n_in,
                              void* d_out, int out_size) {
    const float* in_feats = (const float*)d_in[0];   // [1200,256]
    const float* feat_map = (const float*)d_in[1];   // [4,256,160,160]
    const float* qry_w    = (const float*)d_in[2];   // [32,256]
    const float* qry_b    = (const float*)d_in[3];   // [32]
    const float* key_w    = (const float*)d_in[4];   // [32,256]
    const float* key_b    = (const float*)d_in[5];   // [32]
    float* out = (float*)d_out;                      // [1200,160,160]

    static const int SMEM = 32768 + 38400;           // 71168 B dynamic
    cudaFuncSetAttribute(seg_kernel, cudaFuncAttributeMaxDynamicSharedMemorySize, SMEM);

    qproj_kernel<<<150, 256>>>(in_feats, qry_w, qry_b);
    seg_kernel<<<BATCH * PIX_BLOCKS, THREADS, SMEM>>>(feat_map, key_w, key_b, out);
}

// round 2
// speedup vs baseline: 1.1084x; 1.1084x over previous
#include <cuda_runtime.h>
#include <cuda_bf16.h>

// Problem constants (fixed shapes per reference)
#define BATCH    4
#define N_PER    300
#define IN_DIM   256
#define KEY_DIM  32
#define HW       25600          // 160*160
#define THREADS  128
#define PIX_PER_BLOCK 256       // 128 threads x 2 pixels
#define BLOCKS_PER_B  100       // 25600 / 256

typedef unsigned long long ull;

__device__ __forceinline__ ull pack2(float lo, float hi) {
    ull r; asm("mov.b64 %0, {%1,%2};" : "=l"(r) : "f"(lo), "f"(hi)); return r;
}
__device__ __forceinline__ void unpack2(ull v, float& lo, float& hi) {
    asm("mov.b64 {%0,%1}, %2;" : "=f"(lo), "=f"(hi) : "l"(v));
}
__device__ __forceinline__ ull fma2(ull a, ull b, ull c) {
    ull d; asm("fma.rn.f32x2 %0, %1, %2, %3;" : "=l"(d) : "l"(a), "l"(b), "l"(c)); return d;
}
__device__ __forceinline__ ull add2(ull a, ull b) {
    ull d; asm("add.rn.f32x2 %0, %1, %2;" : "=l"(d) : "l"(a), "l"(b)); return d;
}
__device__ __forceinline__ float hsum2(ull v) {
    float lo, hi; unpack2(v, lo, hi); return lo + hi;
}

// q projection result: [1200][32]
__device__ float g_q[BATCH * N_PER * KEY_DIM];

// ---------------------------------------------------------------------------
// Kernel 1: q = in_feats @ qry_w^T + qry_b    (tiny: 1200x32x256)
// One warp per 4 rows (weight loads amortized x4); lane = output channel o.
// ---------------------------------------------------------------------------
__global__ void qproj_kernel(const float* __restrict__ in_feats,
                             const float* __restrict__ qry_w,
                             const float* __restrict__ qry_b) {
    int warp = threadIdx.x >> 5;
    int lane = threadIdx.x & 31;
    int row0 = (blockIdx.x * 8 + warp) * 4;       // grid=38 blocks x 8 warps x 4 rows
    if (row0 >= BATCH * N_PER) return;

    const float4* qw4 = (const float4*)(qry_w + (size_t)lane * IN_DIM);
    const float4* x0 = (const float4*)(in_feats + (size_t)(row0 + 0) * IN_DIM);
    const float4* x1 = (const float4*)(in_feats + (size_t)(row0 + 1) * IN_DIM);
    const float4* x2 = (const float4*)(in_feats + (size_t)(row0 + 2) * IN_DIM);
    const float4* x3 = (const float4*)(in_feats + (size_t)(row0 + 3) * IN_DIM);

    float a0 = 0.f, a1 = 0.f, a2 = 0.f, a3 = 0.f;
#pragma unroll 4
    for (int i = 0; i < IN_DIM / 4; i++) {
        float4 w = qw4[i];
        float4 v;
        v = x0[i]; a0 = fmaf(v.x, w.x, fmaf(v.y, w.y, fmaf(v.z, w.z, fmaf(v.w, w.w, a0))));
        v = x1[i]; a1 = fmaf(v.x, w.x, fmaf(v.y, w.y, fmaf(v.z, w.z, fmaf(v.w, w.w, a1))));
        v = x2[i]; a2 = fmaf(v.x, w.x, fmaf(v.y, w.y, fmaf(v.z, w.z, fmaf(v.w, w.w, a2))));
        v = x3[i]; a3 = fmaf(v.x, w.x, fmaf(v.y, w.y, fmaf(v.z, w.z, fmaf(v.w, w.w, a3))));
    }
    float bb = qry_b[lane];
    g_q[(row0 + 0) * KEY_DIM + lane] = a0 + bb;
    g_q[(row0 + 1) * KEY_DIM + lane] = a1 + bb;
    g_q[(row0 + 2) * KEY_DIM + lane] = a2 + bb;
    g_q[(row0 + 3) * KEY_DIM + lane] = a3 + bb;
}

// ---------------------------------------------------------------------------
// Kernel 2 (fused), 2 pixels per thread (2t, 2t+1):
//   key_px[o] = sum_c key_w[o,c]*feat[b,c,px] + key_b[o]   (c-pair f32x2 lanes)
//   out[b,n,px] = sum_o q[b,n,o]*key_px[o]                 (o-pair f32x2 lanes)
// Every weight/q LDS.128 now feeds 4 FFMA2 (2 per pixel) -> FMA-pipe bound.
// ---------------------------------------------------------------------------
__global__ __launch_bounds__(THREADS, 3)
void seg_kernel(const float* __restrict__ feat_map,
                const float* __restrict__ key_w,
                const float* __restrict__ key_b,
                float* __restrict__ out) {
    extern __shared__ char smem_raw[];
    float* kw_s = (float*)smem_raw;                 // 32*256 f32 = 32768 B
    float* q_s  = (float*)(smem_raw + 32768);       // 300*32 f32 = 38400 B

    const int tid = threadIdx.x;
    const int b    = blockIdx.x / BLOCKS_PER_B;
    const int tile = blockIdx.x % BLOCKS_PER_B;
    const int p0   = tile * PIX_PER_BLOCK + 2 * tid;   // this thread: pixels p0, p0+1

    // Stage key_w [o][c] and q[b] into smem
    {
        const float4* src = (const float4*)key_w;
        float4* dst = (float4*)kw_s;
        for (int i = tid; i < (KEY_DIM * IN_DIM) / 4; i += THREADS) dst[i] = src[i];
        const float4* qsrc = (const float4*)(g_q + (size_t)b * N_PER * KEY_DIM);
        float4* qdst = (float4*)q_s;
        for (int i = tid; i < (N_PER * KEY_DIM) / 4; i += THREADS) qdst[i] = qsrc[i];
    }
    __syncthreads();

    const float2* fm = (const float2*)(feat_map + (size_t)b * IN_DIM * HW + p0);
    // fm[c * HW/2] = {feat[c][p0], feat[c][p0+1]}

    // Accumulators: c-pair lanes, separate set per pixel. Bias folded in.
    ull acc0[KEY_DIM], acc1[KEY_DIM];
#pragma unroll
    for (int o = 0; o < KEY_DIM; o++) {
        float kb = key_b[o];
        acc0[o] = pack2(kb, 0.f);
        acc1[o] = pack2(kb, 0.f);
    }

    const ulonglong2* kwv = (const ulonglong2*)kw_s; // [o][cq]: {w[c],w[c+1]},{w[c+2],w[c+3]}

    // -------- Stage 1: 64 channel-quads, pipelined float2 feat loads --------
    float2 g0 = fm[0 * (HW / 2)];
    float2 g1 = fm[1 * (HW / 2)];
    float2 g2 = fm[2 * (HW / 2)];
    float2 g3 = fm[3 * (HW / 2)];
    for (int cq = 0; cq < 64; cq++) {
        ull fd01_0 = pack2(g0.x, g1.x);   // pixel0: {f[c],f[c+1]}
        ull fd23_0 = pack2(g2.x, g3.x);
        ull fd01_1 = pack2(g0.y, g1.y);   // pixel1
        ull fd23_1 = pack2(g2.y, g3.y);

        int c4 = 4 * cq + 4;
        if (c4 > 252) c4 = 252;           // branchless tail (redundant reload)
        float2 n0 = fm[(size_t)(c4 + 0) * (HW / 2)];
        float2 n1 = fm[(size_t)(c4 + 1) * (HW / 2)];
        float2 n2 = fm[(size_t)(c4 + 2) * (HW / 2)];
        float2 n3 = fm[(size_t)(c4 + 3) * (HW / 2)];

#pragma unroll
        for (int o = 0; o < KEY_DIM; o++) {
            ulonglong2 w = kwv[o * 64 + cq];      // one broadcast LDS.128 -> 4 FFMA2
            acc0[o] = fma2(fd01_0, w.x, acc0[o]);
            acc0[o] = fma2(fd23_0, w.y, acc0[o]);
            acc1[o] = fma2(fd01_1, w.x, acc1[o]);
            acc1[o] = fma2(fd23_1, w.y, acc1[o]);
        }
        g0 = n0; g1 = n1; g2 = n2; g3 = n3;
    }

    // -------- Repack: kpX[k] = {key[2k], key[2k+1]} per pixel --------
    ull kp0[KEY_DIM / 2], kp1[KEY_DIM / 2];
#pragma unroll
    for (int k = 0; k < KEY_DIM / 2; k++) {
        kp0[k] = pack2(hsum2(acc0[2 * k]), hsum2(acc0[2 * k + 1]));
        kp1[k] = pack2(hsum2(acc1[2 * k]), hsum2(acc1[2 * k + 1]));
    }

    // -------- Stage 2: out[n] = sum_o q[n,o]*key[o] for both pixels --------
    const ulonglong2* qv = (const ulonglong2*)q_s;    // 8 x ulonglong2 per n
    float2* optr = (float2*)(out + (size_t)b * N_PER * HW + p0);

    for (int n = 0; n < N_PER; n++) {
        const ulonglong2* qn = qv + n * 8;
        ull sa0 = 0ull, sb0 = 0ull;   // pixel0, two chains
        ull sa1 = 0ull, sb1 = 0ull;   // pixel1
#pragma unroll
        for (int j = 0; j < 8; j++) {
            ulonglong2 qq = qn[j];                // one broadcast LDS.128 -> 4 FFMA2
            sa0 = fma2(kp0[2 * j],     qq.x, sa0);
            sb0 = fma2(kp0[2 * j + 1], qq.y, sb0);
            sa1 = fma2(kp1[2 * j],     qq.x, sa1);
            sb1 = fma2(kp1[2 * j + 1], qq.y, sb1);
        }
        float2 r;
        r.x = hsum2(add2(sa0, sb0));
        r.y = hsum2(add2(sa1, sb1));
        optr[0] = r;                              // STG.64, coalesced
        optr += HW / 2;
    }
}

// ---------------------------------------------------------------------------
extern "C" void kernel_launch(void* const* d_in, const int* in_sizes, int n_in,
                              void* d_out, int out_size) {
    const float* in_feats = (const float*)d_in[0];   // [1200,256]
    const float* feat_map = (const float*)d_in[1];   // [4,256,160,160]
    const float* qry_w    = (const float*)d_in[2];   // [32,256]
    const float* qry_b    = (const float*)d_in[3];   // [32]
    const float* key_w    = (const float*)d_in[4];   // [32,256]
    const float* key_b    = (const float*)d_in[5];   // [32]
    float* out = (float*)d_out;                      // [1200,160,160]

    static const int SMEM = 32768 + 38400;           // 71168 B dynamic
    cudaFuncSetAttribute(seg_kernel, cudaFuncAttributeMaxDynamicSharedMemorySize, SMEM);

    qproj_kernel<<<38, 256>>>(in_feats, qry_w, qry_b);
    seg_kernel<<<BATCH * BLOCKS_PER_B, THREADS, SMEM>>>(feat_map, key_w, key_b, out);
}

// round 3
// speedup vs baseline: 1.3030x; 1.1757x over previous
#include <cuda_runtime.h>
#include <cuda_bf16.h>

// Fixed problem shapes
#define BATCH   4
#define N_PER   300
#define IN_DIM  256
#define KEY_DIM 32
#define NJ      16          // o-pairs (KEY_DIM/2)
#define HW      25600       // 160*160
#define PX_TILE 256
#define THREADS 256
#define N_PAD   320         // padded n for phase-B passes (10 passes x 32)

typedef unsigned long long ull;

__device__ __forceinline__ ull pack2(float lo, float hi) {
    ull r; asm("mov.b64 %0, {%1,%2};" : "=l"(r) : "f"(lo), "f"(hi)); return r;
}
__device__ __forceinline__ ull fma2(ull a, ull b, ull c) {
    ull d; asm("fma.rn.f32x2 %0, %1, %2, %3;" : "=l"(d) : "l"(a), "l"(b), "l"(c)); return d;
}
__device__ __forceinline__ float hsum2(ull v) {
    float lo, hi; asm("mov.b64 {%0,%1}, %2;" : "=f"(lo), "=f"(hi) : "l"(v));
    return lo + hi;
}

// Pre-packed operands (o-pair lanes, lane0 = even o)
__device__ ull g_qp[BATCH * NJ * N_PER];   // {q[n][2J], q[n][2J+1]}  layout [b][J][n]
__device__ ull g_kwp[IN_DIM * NJ];         // {kw[2J][c], kw[2J+1][c]} layout [c][J]

// ---------------------------------------------------------------------------
// Prep: q = in_feats @ qry_w^T + qry_b, written as o-pair ulls; also packs kw.
// grid 150 x 256: warp = one row, lane = output channel o.
// ---------------------------------------------------------------------------
__global__ void prep_kernel(const float* __restrict__ in_feats,
                            const float* __restrict__ qry_w,
                            const float* __restrict__ qry_b,
                            const float* __restrict__ key_w) {
    // kw pair-pack folded into the first 16 blocks (4096 elements)
    if (blockIdx.x < 16) {
        int idx = blockIdx.x * 256 + threadIdx.x;       // 0..4095
        int c = idx >> 4, J = idx & 15;
        g_kwp[idx] = pack2(key_w[(2 * J) * IN_DIM + c],
                           key_w[(2 * J + 1) * IN_DIM + c]);
    }

    int warp = threadIdx.x >> 5, lane = threadIdx.x & 31;
    int row  = blockIdx.x * 8 + warp;                   // 0..1199

    const float4* x = (const float4*)(in_feats + (size_t)row * IN_DIM);
    const float4* w = (const float4*)(qry_w    + (size_t)lane * IN_DIM);
    float a0 = 0.f, a1 = 0.f;
#pragma unroll 8
    for (int i = 0; i < IN_DIM / 4; i++) {
        float4 xv = x[i], wv = w[i];
        a0 = fmaf(xv.x, wv.x, a0); a1 = fmaf(xv.y, wv.y, a1);
        a0 = fmaf(xv.z, wv.z, a0); a1 = fmaf(xv.w, wv.w, a1);
    }
    float q = a0 + a1 + qry_b[lane];
    int b = row / N_PER, n = row - b * N_PER;
    float* dst = (float*)(g_qp + ((size_t)b * NJ + (lane >> 1)) * N_PER + n);
    dst[lane & 1] = q;
}

// ---------------------------------------------------------------------------
// Fused seg kernel, one block = 256 pixels of one batch image.
// Phase A: key_s[J][px] (o-pair ulls) = kw @ feat + kb   (register-tiled 8Jx2px)
// Phase B: out[n][px]  = sum_J pairdot(q[n][J], key[J][px])  (tiled 8n x 4px)
// ---------------------------------------------------------------------------
__global__ __launch_bounds__(THREADS, 2)
void seg_kernel(const float* __restrict__ feat_map,
                const float* __restrict__ key_b,
                float* __restrict__ out) {
    extern __shared__ char sm[];
    ull*   key_s  = (ull*)sm;                    // [16][256] ull  : 32768 B
    float* feat_s = (float*)(sm + 32768);        // [32][256] f32  : 32768 B
    ull*   kw_s   = (ull*)(sm + 65536);          // [32][16]  ull  :  4096 B
    ull*   q_s    = (ull*)(sm + 69632);          // [16][320] ull  : 40960 B
                                                 // total 110592 B

    const int tid = threadIdx.x;
    const int b   = blockIdx.y;
    const int p0  = blockIdx.x * PX_TILE;

    // ---- stage q (once): [J][n] padded to 320 with zeros ----
    {
        const ull* qp = g_qp + (size_t)b * NJ * N_PER;
        for (int i = tid; i < NJ * N_PAD; i += THREADS) {
            int J = i / N_PAD, n = i - J * N_PAD;
            q_s[i] = (n < N_PER) ? qp[J * N_PER + n] : 0ull;
        }
    }

    // ---- Phase A: thread = 8 o-pairs (Jb..Jb+7) x 2 px (txA, txA+128) ----
    const int txA = tid & 127;
    const int Jb  = (tid >> 7) * 8;              // 0 or 8

    ull acc[8][2];
#pragma unroll
    for (int j = 0; j < 8; j++) {
        ull kb = *(const ull*)(key_b + 2 * (Jb + j));   // {kb[2J], kb[2J+1]}
        acc[j][0] = kb; acc[j][1] = kb;
    }

    const float* fm_base = feat_map + (size_t)b * IN_DIM * HW + p0;

    for (int chunk = 0; chunk < 8; chunk++) {
        __syncthreads();                          // protect prev chunk reads
        // stage feat chunk [32 c][256 px]
        {
            int c0  = tid >> 6;                   // 0..3
            int px4 = (tid & 63) * 4;             // 0..252 step 4
#pragma unroll
            for (int j = 0; j < 8; j++) {
                int c = c0 + j * 4;
                float4 v = *(const float4*)(fm_base + (size_t)(chunk * 32 + c) * HW + px4);
                *(float4*)(feat_s + c * 256 + px4) = v;
            }
            // stage kw chunk [32 c][16 J] ull = 256 float4
            ((float4*)kw_s)[tid] = ((const float4*)(g_kwp + (size_t)chunk * 32 * NJ))[tid];
        }
        __syncthreads();

#pragma unroll 8
        for (int c = 0; c < 32; c++) {
            const ull* kwc = kw_s + c * NJ + Jb;
            ull w[8];
#pragma unroll
            for (int j = 0; j < 8; j++) w[j] = kwc[j];       // 4x LDS.128 bcast
            float f0 = feat_s[c * 256 + txA];
            float f1 = feat_s[c * 256 + txA + 128];
            ull d0 = pack2(f0, f0);
            ull d1 = pack2(f1, f1);
#pragma unroll
            for (int j = 0; j < 8; j++) {
                acc[j][0] = fma2(d0, w[j], acc[j][0]);
                acc[j][1] = fma2(d1, w[j], acc[j][1]);
            }
        }
    }

    // write key tile: key_s[J][px] (ull o-pairs), conflict-free STS.64
#pragma unroll
    for (int j = 0; j < 8; j++) {
        key_s[(Jb + j) * 256 + txA]       = acc[j][0];
        key_s[(Jb + j) * 256 + txA + 128] = acc[j][1];
    }
    __syncthreads();

    // ---- Phase B: thread = 8 n x 4 px (px = txB + 64k), reduce over 16 J ----
    const int txB = tid & 63;
    const int tyB = tid >> 6;                    // 0..3
    float* outb = out + (size_t)b * N_PER * HW + p0 + txB;

    for (int pass = 0; pass < 10; pass++) {
        const int nb = pass * 32 + tyB * 8;
        ull s[8][4];
#pragma unroll
        for (int i = 0; i < 8; i++)
#pragma unroll
            for (int k = 0; k < 4; k++) s[i][k] = 0ull;

#pragma unroll 4
        for (int J = 0; J < NJ; J++) {
            const ull* qp = q_s + J * N_PAD + nb;
            ull qv[8];
#pragma unroll
            for (int i = 0; i < 8; i++) qv[i] = qp[i];       // 4x LDS.128 bcast
            const ull* kp = key_s + J * 256 + txB;
            ull k0 = kp[0], k1 = kp[64], k2 = kp[128], k3 = kp[192];
#pragma unroll
            for (int i = 0; i < 8; i++) {
                s[i][0] = fma2(qv[i], k0, s[i][0]);
                s[i][1] = fma2(qv[i], k1, s[i][1]);
                s[i][2] = fma2(qv[i], k2, s[i][2]);
                s[i][3] = fma2(qv[i], k3, s[i][3]);
            }
        }

#pragma unroll
        for (int i = 0; i < 8; i++) {
            int n = nb + i;
            if (n < N_PER) {
                float* o = outb + (size_t)n * HW;
                o[0]   = hsum2(s[i][0]);
                o[64]  = hsum2(s[i][1]);
                o[128] = hsum2(s[i][2]);
                o[192] = hsum2(s[i][3]);
            }
        }
    }
}

// ---------------------------------------------------------------------------
extern "C" void kernel_launch(void* const* d_in, const int* in_sizes, int n_in,
                              void* d_out, int out_size) {
    const float* in_feats = (const float*)d_in[0];   // [1200,256]
    const float* feat_map = (const float*)d_in[1];   // [4,256,160,160]
    const float* qry_w    = (const float*)d_in[2];   // [32,256]
    const float* qry_b    = (const float*)d_in[3];   // [32]
    const float* key_w    = (const float*)d_in[4];   // [32,256]
    const float* key_b    = (const float*)d_in[5];   // [32]
    float* out = (float*)d_out;                      // [1200,160,160]

    static const int SMEM = 110592;
    cudaFuncSetAttribute(seg_kernel, cudaFuncAttributeMaxDynamicSharedMemorySize, SMEM);

    prep_kernel<<<150, 256>>>(in_feats, qry_w, qry_b, key_w);
    dim3 grid(HW / PX_TILE, BATCH);                  // (100, 4)
    seg_kernel<<<grid, THREADS, SMEM>>>(feat_map, key_b, out);
}

// round 4
// speedup vs baseline: 1.4977x; 1.1494x over previous
#include <cuda_runtime.h>
#include <cuda_bf16.h>

// Fixed problem shapes
#define BATCH   4
#define N_PER   300
#define IN_DIM  256
#define KEY_DIM 32
#define NJ      16          // o-pairs (KEY_DIM/2)
#define HW      25600       // 160*160
#define PX_TILE 256
#define THREADS 256
#define N_PAD   320         // padded n (10 passes x 32)
#define C_CHUNK 16          // channels per pipeline chunk
#define NCHUNK  16          // IN_DIM / C_CHUNK

typedef unsigned long long ull;

__device__ __forceinline__ ull pack2(float lo, float hi) {
    ull r; asm("mov.b64 %0, {%1,%2};" : "=l"(r) : "f"(lo), "f"(hi)); return r;
}
__device__ __forceinline__ ull fma2(ull a, ull b, ull c) {
    ull d; asm("fma.rn.f32x2 %0, %1, %2, %3;" : "=l"(d) : "l"(a), "l"(b), "l"(c)); return d;
}
__device__ __forceinline__ float hsum2(ull v) {
    float lo, hi; asm("mov.b64 {%0,%1}, %2;" : "=f"(lo), "=f"(hi) : "l"(v));
    return lo + hi;
}
__device__ __forceinline__ void cp16(unsigned smem_addr, const void* gptr) {
    asm volatile("cp.async.cg.shared.global [%0], [%1], 16;"
                 :: "r"(smem_addr), "l"(gptr));
}
#define CP_COMMIT() asm volatile("cp.async.commit_group;" ::: "memory")
#define CP_WAIT_ALL() asm volatile("cp.async.wait_group 0;" ::: "memory")

// Pre-packed operands (o-pair lanes)
__device__ ull g_qp[BATCH * NJ * N_PER];   // layout [b][J][n] : {q[n][2J], q[n][2J+1]}
__device__ ull g_kwp[IN_DIM * NJ];         // layout [c][J]    : {kw[2J][c], kw[2J+1][c]}

// ---------------------------------------------------------------------------
// Prep: q = in_feats @ qry_w^T + qry_b (o-pair packed); also packs kw.
// ---------------------------------------------------------------------------
__global__ void prep_kernel(const float* __restrict__ in_feats,
                            const float* __restrict__ qry_w,
                            const float* __restrict__ qry_b,
                            const float* __restrict__ key_w) {
    if (blockIdx.x < 16) {
        int idx = blockIdx.x * 256 + threadIdx.x;       // 0..4095
        int c = idx >> 4, J = idx & 15;
        g_kwp[idx] = pack2(key_w[(2 * J) * IN_DIM + c],
                           key_w[(2 * J + 1) * IN_DIM + c]);
    }
    int warp = threadIdx.x >> 5, lane = threadIdx.x & 31;
    int row  = blockIdx.x * 8 + warp;                   // 0..1199

    const float4* x = (const float4*)(in_feats + (size_t)row * IN_DIM);
    const float4* w = (const float4*)(qry_w    + (size_t)lane * IN_DIM);
    float a0 = 0.f, a1 = 0.f;
#pragma unroll 8
    for (int i = 0; i < IN_DIM / 4; i++) {
        float4 xv = x[i], wv = w[i];
        a0 = fmaf(xv.x, wv.x, a0); a1 = fmaf(xv.y, wv.y, a1);
        a0 = fmaf(xv.z, wv.z, a0); a1 = fmaf(xv.w, wv.w, a1);
    }
    float q = a0 + a1 + qry_b[lane];
    int b = row / N_PER, n = row - b * N_PER;
    float* dst = (float*)(g_qp + ((size_t)b * NJ + (lane >> 1)) * N_PER + n);
    dst[lane & 1] = q;
}

// ---------------------------------------------------------------------------
// Fused seg kernel: one block = 256 px of one image.
// Phase A (cp.async pipelined): key_s[J][px] = kw @ feat + kb
// Phase B: out[n][px] = sum_J pairdot(q[n][J], key[J][px])
// ---------------------------------------------------------------------------
__global__ __launch_bounds__(THREADS, 2)
void seg_kernel(const float* __restrict__ feat_map,
                const float* __restrict__ key_b,
                float* __restrict__ out) {
    extern __shared__ char sm[];
    ull*   key_s  = (ull*)sm;                      // [16][256] ull : 32768 B
    float* feat_s = (float*)(sm + 32768);          // 2 x [16][256] : 32768 B
    ull*   kw_s   = (ull*)(sm + 65536);            // 2 x [16][16]  :  4096 B
    ull*   q_s    = (ull*)(sm + 69632);            // [16][320] ull : 40960 B
                                                   // total 110592 B
    const int tid = threadIdx.x;
    const int b   = blockIdx.y;
    const int p0  = blockIdx.x * PX_TILE;

    const unsigned feat_sa = (unsigned)__cvta_generic_to_shared(feat_s);
    const unsigned kw_sa   = (unsigned)__cvta_generic_to_shared(kw_s);
    const float* fm_base = feat_map + (size_t)b * IN_DIM * HW + p0;

    // ---- stage q (once): [J][n] padded to 320 ----
    {
        const ull* qp = g_qp + (size_t)b * NJ * N_PER;
        for (int i = tid; i < NJ * N_PAD; i += THREADS) {
            int J = i / N_PAD, n = i - J * N_PAD;
            q_s[i] = (n < N_PER) ? qp[J * N_PER + n] : 0ull;
        }
    }

    // ---- Phase A pipeline ----
    const int txA = tid & 127;
    const int Jb  = (tid >> 7) * 8;               // 0 or 8

    ull acc[8][2];
#pragma unroll
    for (int j = 0; j < 8; j++) {
        ull kb = *(const ull*)(key_b + 2 * (Jb + j));
        acc[j][0] = kb; acc[j][1] = kb;
    }

    // issue chunk 0
    {
#pragma unroll
        for (int i = 0; i < 4; i++) {
            int f = i * 256 + tid;                // float4 index in [16c][64]
            int c = f >> 6, px4 = f & 63;
            cp16(feat_sa + (unsigned)(c * 1024 + px4 * 16),
                 fm_base + (size_t)c * HW + px4 * 4);
        }
        if (tid < 128)
            cp16(kw_sa + (unsigned)tid * 16, (const char*)g_kwp + tid * 16);
        CP_COMMIT();
    }

    for (int k = 0; k < NCHUNK; k++) {
        CP_WAIT_ALL();
        __syncthreads();                          // chunk k ready; k-1 compute done
        const int buf = k & 1, nbuf = buf ^ 1;

        if (k + 1 < NCHUNK) {                     // issue chunk k+1
            const float* src = fm_base + (size_t)(k + 1) * C_CHUNK * HW;
#pragma unroll
            for (int i = 0; i < 4; i++) {
                int f = i * 256 + tid;
                int c = f >> 6, px4 = f & 63;
                cp16(feat_sa + (unsigned)(nbuf * 16384 + c * 1024 + px4 * 16),
                     src + (size_t)c * HW + px4 * 4);
            }
            if (tid < 128)
                cp16(kw_sa + (unsigned)(nbuf * 2048 + tid * 16),
                     (const char*)(g_kwp + (size_t)(k + 1) * C_CHUNK * NJ) + tid * 16);
            CP_COMMIT();
        }

        const float* fs = feat_s + buf * 4096;
        const ull*   ks = kw_s + buf * 256;
#pragma unroll
        for (int c = 0; c < C_CHUNK; c++) {
            const ull* kwc = ks + c * NJ + Jb;
            ull w[8];
#pragma unroll
            for (int j = 0; j < 8; j++) w[j] = kwc[j];   // 4x LDS.128 bcast
            float f0 = fs[c * 256 + txA];
            float f1 = fs[c * 256 + txA + 128];
            ull d0 = pack2(f0, f0);
            ull d1 = pack2(f1, f1);
#pragma unroll
            for (int j = 0; j < 8; j++) {
                acc[j][0] = fma2(d0, w[j], acc[j][0]);
                acc[j][1] = fma2(d1, w[j], acc[j][1]);
            }
        }
    }

    __syncthreads();                              // everyone done with feat bufs
    // write key tile [J][px]
#pragma unroll
    for (int j = 0; j < 8; j++) {
        key_s[(Jb + j) * 256 + txA]       = acc[j][0];
        key_s[(Jb + j) * 256 + txA + 128] = acc[j][1];
    }
    __syncthreads();

    // ---- Phase B: thread = 8 n x 4 px {2t, 2t+1, 2t+128, 2t+129} ----
    const int txB = tid & 63;                     // pixel pair id
    const int tyB = tid >> 6;                     // 0..3
    float* outb = out + (size_t)b * N_PER * HW + p0 + 2 * txB;

    for (int pass = 0; pass < 10; pass++) {
        const int nb = pass * 32 + tyB * 8;
        ull s[8][4];
#pragma unroll
        for (int i = 0; i < 8; i++)
#pragma unroll
            for (int kk = 0; kk < 4; kk++) s[i][kk] = 0ull;

#pragma unroll 4
        for (int J = 0; J < NJ; J++) {
            const ull* qp = q_s + J * N_PAD + nb;
            ull qv[8];
#pragma unroll
            for (int i = 0; i < 8; i++) qv[i] = qp[i];   // 4x LDS.128 bcast
            ulonglong2 k01 = *(const ulonglong2*)(key_s + J * 256 + 2 * txB);
            ulonglong2 k23 = *(const ulonglong2*)(key_s + J * 256 + 2 * txB + 128);
#pragma unroll
            for (int i = 0; i < 8; i++) {
                s[i][0] = fma2(qv[i], k01.x, s[i][0]);
                s[i][1] = fma2(qv[i], k01.y, s[i][1]);
                s[i][2] = fma2(qv[i], k23.x, s[i][2]);
                s[i][3] = fma2(qv[i], k23.y, s[i][3]);
            }
        }

#pragma unroll
        for (int i = 0; i < 8; i++) {
            int n = nb + i;
            if (n < N_PER) {
                float* o = outb + (size_t)n * HW;
                float2 r0; r0.x = hsum2(s[i][0]); r0.y = hsum2(s[i][1]);
                float2 r1; r1.x = hsum2(s[i][2]); r1.y = hsum2(s[i][3]);
                *(float2*)o         = r0;         // STG.64, coalesced
                *(float2*)(o + 128) = r1;
            }
        }
    }
}

// ---------------------------------------------------------------------------
extern "C" void kernel_launch(void* const* d_in, const int* in_sizes, int n_in,
                              void* d_out, int out_size) {
    const float* in_feats = (const float*)d_in[0];   // [1200,256]
    const float* feat_map = (const float*)d_in[1];   // [4,256,160,160]
    const float* qry_w    = (const float*)d_in[2];   // [32,256]
    const float* qry_b    = (const float*)d_in[3];   // [32]
    const float* key_w    = (const float*)d_in[4];   // [32,256]
    const float* key_b    = (const float*)d_in[5];   // [32]
    float* out = (float*)d_out;                      // [1200,160,160]

    static const int SMEM = 110592;
    cudaFuncSetAttribute(seg_kernel, cudaFuncAttributeMaxDynamicSharedMemorySize, SMEM);

    prep_kernel<<<150, 256>>>(in_feats, qry_w, qry_b, key_w);
    dim3 grid(HW / PX_TILE, BATCH);                  // (100, 4)
    seg_kernel<<<grid, THREADS, SMEM>>>(feat_map, key_b, out);
}

// round 6
// speedup vs baseline: 2.1969x; 1.4669x over previous
#include <cuda_runtime.h>
#include <cstdint>

// Fixed problem shapes
#define BATCH   4
#define N_PER   300
#define IN_DIM  256
#define KEY_DIM 32
#define HW      25600       // 160*160
#define THREADS 256
#define NT1     4           // stage1 n-tiles (o: 32/8)
#define NT2P    40          // stage2 n-tiles padded (304->320)
#define FSTR    132         // feat/key smem row stride (floats): banks (8t+g) conflict-free

// smem byte offsets
#define SM_FEAT0 0
#define SM_FEAT1 16896      // 32*132*4
#define SM_KEY   0          // key tile [32 o][132] overlaps feat buf0 (dead by then)
#define SM_KWF   33792
#define SM_QF    66560      // 33792 + 32768
#define SM_TOTAL 107520     // 66560 + 40*2*32*16

typedef unsigned int u32;

// Fragment-packed weights: {b0_hi, b1_hi, b0_lo, b1_lo} bf16x2 each
__device__ uint4 g_kwf[16 * 4 * 32];            // [kt16][nt][lane]
__device__ uint4 g_qf[BATCH * 2 * NT2P * 32];   // [b][kt16][nt][lane]
__device__ float g_q[BATCH * N_PER * KEY_DIM];  // fp32 q projection

// ---------------------------------------------------------------------------
__device__ __forceinline__ u32 packbf(float flo, float fhi) {
    u32 r; asm("cvt.rn.bf16x2.f32 %0, %1, %2;" : "=r"(r) : "f"(fhi), "f"(flo));
    return r;   // low half = bf16(flo), high half = bf16(fhi)
}
__device__ __forceinline__ u32 split_pair(float f0, float f1, u32& lo) {
    u32 h = packbf(f0, f1);
    float h0 = __uint_as_float(h << 16);
    float h1 = __uint_as_float(h & 0xffff0000u);
    lo = packbf(f0 - h0, f1 - h1);
    return h;
}
__device__ __forceinline__ void mma_bf16(float d[4], const u32 a[4], u32 b0, u32 b1) {
    asm volatile(
        "mma.sync.aligned.m16n8k16.row.col.f32.bf16.bf16.f32 "
        "{%0,%1,%2,%3}, {%4,%5,%6,%7}, {%8,%9}, {%0,%1,%2,%3};"
        : "+f"(d[0]), "+f"(d[1]), "+f"(d[2]), "+f"(d[3])
        : "r"(a[0]), "r"(a[1]), "r"(a[2]), "r"(a[3]), "r"(b0), "r"(b1));
}
__device__ __forceinline__ void cp16(u32 saddr, const void* g) {
    asm volatile("cp.async.cg.shared.global [%0], [%1], 16;" :: "r"(saddr), "l"(g));
}
#define CP_COMMIT()  asm volatile("cp.async.commit_group;" ::: "memory")
#define CP_WAITALL() asm volatile("cp.async.wait_group 0;" ::: "memory")

// ---------------------------------------------------------------------------
// Prep 1: q = in_feats @ qry_w^T + qry_b  (fp32)
// ---------------------------------------------------------------------------
__global__ void qproj_kernel(const float* __restrict__ in_feats,
                             const float* __restrict__ qry_w,
                             const float* __restrict__ qry_b) {
    int warp = threadIdx.x >> 5, lane = threadIdx.x & 31;
    int row  = blockIdx.x * 8 + warp;       // 150 blocks x 8 = 1200

    const float4* x = (const float4*)(in_feats + (size_t)row * IN_DIM);
    const float4* w = (const float4*)(qry_w    + (size_t)lane * IN_DIM);
    float a0 = 0.f, a1 = 0.f;
#pragma unroll 8
    for (int i = 0; i < IN_DIM / 4; i++) {
        float4 xv = x[i], wv = w[i];
        a0 = fmaf(xv.x, wv.x, a0); a1 = fmaf(xv.y, wv.y, a1);
        a0 = fmaf(xv.z, wv.z, a0); a1 = fmaf(xv.w, wv.w, a1);
    }
    g_q[row * KEY_DIM + lane] = a0 + a1 + qry_b[lane];
}

// ---------------------------------------------------------------------------
// Prep 2: pack kw and q into hi/lo bf16 fragment-linear layouts.
// B frag (m16n8k16 col-major): b0 = {B[2t][g],B[2t+1][g]}, b1 = {B[2t+8][g],B[2t+9][g]}
// ---------------------------------------------------------------------------
__global__ void pack_kernel(const float* __restrict__ key_w) {
    int idx = blockIdx.x * 256 + threadIdx.x;
    if (idx < 16 * 4 * 32) {                        // kwf: kt16 x nt x lane
        int lane = idx & 31, nt = (idx >> 5) & 3, kt = idx >> 7;
        int t = lane & 3, g = lane >> 2;
        int o = nt * 8 + g;
        int k0 = kt * 16 + 2 * t;
        float w00 = key_w[o * IN_DIM + k0],     w01 = key_w[o * IN_DIM + k0 + 1];
        float w10 = key_w[o * IN_DIM + k0 + 8], w11 = key_w[o * IN_DIM + k0 + 9];
        uint4 v;
        v.x = split_pair(w00, w01, v.z);
        v.y = split_pair(w10, w11, v.w);
        g_kwf[idx] = v;
    }
    int qi = idx - 16 * 4 * 32;
    if (qi >= 0 && qi < BATCH * 2 * NT2P * 32) {    // qf: b x kt16 x nt x lane
        int lane = qi & 31;
        int nt   = (qi >> 5) % NT2P;
        int rest = qi / (32 * NT2P);
        int kt = rest & 1, b = rest >> 1;
        int t = lane & 3, g = lane >> 2;
        int n  = nt * 8 + g;
        int o0 = kt * 16 + 2 * t;
        float q00 = 0.f, q01 = 0.f, q10 = 0.f, q11 = 0.f;
        if (n < N_PER) {
            const float* qr = g_q + ((size_t)b * N_PER + n) * KEY_DIM;
            q00 = qr[o0];     q01 = qr[o0 + 1];
            q10 = qr[o0 + 8]; q11 = qr[o0 + 9];
        }
        uint4 v;
        v.x = split_pair(q00, q01, v.z);
        v.y = split_pair(q10, q11, v.w);
        g_qf[qi] = v;
    }
}

// ---------------------------------------------------------------------------
// Fused MMA kernel. One block = 128 px of one image. 8 warps, warp = 16 px rows.
//  Stage 1: D1[px][o]  = feat @ kw^T + key_b   (bf16 split MMA, K=256)
//  Stage 2: D2[px][n]  = key @ q^T             (bf16 split MMA, K=32)
// ---------------------------------------------------------------------------
__global__ void __launch_bounds__(THREADS, 2)
seg_mma(const float* __restrict__ feat_map,
        const float* __restrict__ key_b,
        float* __restrict__ out) {
    extern __shared__ char sm[];
    float* feat_s = (float*)sm;
    float* key_s  = (float*)(sm + SM_KEY);              // [32 o][FSTR px]
    const uint4* kwf_s = (const uint4*)(sm + SM_KWF);
    const uint4* qf_s  = (const uint4*)(sm + SM_QF);

    const int tid  = threadIdx.x;
    const int w    = tid >> 5, lane = tid & 31;
    const int t    = lane & 3, g = lane >> 2;
    const int b    = blockIdx.y;
    const int p0   = blockIdx.x * 128;
    const int colA = 16 * w + g;                        // this lane's px row

    const u32 sb = (u32)__cvta_generic_to_shared(sm);
    const float* fm = feat_map + (size_t)b * IN_DIM * HW + p0;

    // ---- stage kwf, qf(batch), feat chunk 0 via cp.async ----
    for (int i = tid; i < 16 * 4 * 32; i += THREADS)
        cp16(sb + SM_KWF + i * 16, g_kwf + i);
    {
        const uint4* qsrc = g_qf + (size_t)b * 2 * NT2P * 32;
        for (int i = tid; i < 2 * NT2P * 32; i += THREADS)
            cp16(sb + SM_QF + i * 16, qsrc + i);
    }
#pragma unroll
    for (int i = 0; i < 4; i++) {
        int f = i * 256 + tid;
        int row = f >> 5, c4 = f & 31;
        cp16(sb + SM_FEAT0 + row * (FSTR * 4) + c4 * 16,
             fm + (size_t)row * HW + c4 * 4);
    }
    CP_COMMIT();

    // ---- Stage 1: K loop, 8 chunks x 32 c, double buffered ----
    float D1[NT1][4];
#pragma unroll
    for (int nt = 0; nt < NT1; nt++)
#pragma unroll
        for (int i = 0; i < 4; i++) D1[nt][i] = 0.f;

    for (int chunk = 0; chunk < 8; chunk++) {
        CP_WAITALL();
        __syncthreads();
        const int buf = chunk & 1;

        if (chunk + 1 < 8) {
            const float* src = fm + (size_t)(chunk + 1) * 32 * HW;
            const u32 dstb = sb + (buf ^ 1) * SM_FEAT1;
#pragma unroll
            for (int i = 0; i < 4; i++) {
                int f = i * 256 + tid;
                int row = f >> 5, c4 = f & 31;
                cp16(dstb + row * (FSTR * 4) + c4 * 16,
                     src + (size_t)row * HW + c4 * 4);
            }
            CP_COMMIT();
        }

        const float* fb = feat_s + buf * (SM_FEAT1 / 4);
#pragma unroll
        for (int ksl = 0; ksl < 2; ksl++) {
            const int kt = chunk * 2 + ksl;
            const int rb = ksl * 16 + 2 * t;            // c row of k-pair base
            // A fragment: a0:(px=colA, k=2t,2t+1) a1:(px+8) a2:(k+8) a3:(px+8,k+8)
            float f00 = fb[(rb)     * FSTR + colA];
            float f01 = fb[(rb + 1) * FSTR + colA];
            float f10 = fb[(rb)     * FSTR + colA + 8];
            float f11 = fb[(rb + 1) * FSTR + colA + 8];
            float f20 = fb[(rb + 8) * FSTR + colA];
            float f21 = fb[(rb + 9) * FSTR + colA];
            float f30 = fb[(rb + 8) * FSTR + colA + 8];
            float f31 = fb[(rb + 9) * FSTR + colA + 8];
            u32 ah[4], al[4];
            ah[0] = split_pair(f00, f01, al[0]);
            ah[1] = split_pair(f10, f11, al[1]);
            ah[2] = split_pair(f20, f21, al[2]);
            ah[3] = split_pair(f30, f31, al[3]);
#pragma unroll
            for (int nt = 0; nt < NT1; nt++) {
                uint4 B = kwf_s[(kt * 4 + nt) * 32 + lane];
                mma_bf16(D1[nt], ah, B.x, B.y);   // hi*hi
                mma_bf16(D1[nt], al, B.x, B.y);   // lo*hi
                mma_bf16(D1[nt], ah, B.z, B.w);   // hi*lo
            }
        }
    }

    __syncthreads();      // all feat reads done before key_s overwrites buf0
    // ---- epilogue: key_s[o][px] = D1 + key_b ----
#pragma unroll
    for (int nt = 0; nt < NT1; nt++)
#pragma unroll
        for (int i = 0; i < 4; i++) {
            int o  = nt * 8 + 2 * t + (i & 1);
            int px = colA + ((i & 2) ? 8 : 0);
            key_s[o * FSTR + px] = D1[nt][i] + key_b[o];
        }
    __syncthreads();

    // ---- Stage 2: 5 chunks of 8 n-tiles ----
    float* outb = out + (size_t)b * N_PER * HW + p0;

    for (int c5 = 0; c5 < 5; c5++) {
        const int nts = c5 * 8;
        float D2[8][4];
#pragma unroll
        for (int j = 0; j < 8; j++)
#pragma unroll
            for (int i = 0; i < 4; i++) D2[j][i] = 0.f;

#pragma unroll
        for (int kt = 0; kt < 2; kt++) {
            const int rb = kt * 16 + 2 * t;             // o row base
            float k00 = key_s[(rb)     * FSTR + colA];
            float k01 = key_s[(rb + 1) * FSTR + colA];
            float k10 = key_s[(rb)     * FSTR + colA + 8];
            float k11 = key_s[(rb + 1) * FSTR + colA + 8];
            float k20 = key_s[(rb + 8) * FSTR + colA];
            float k21 = key_s[(rb + 9) * FSTR + colA];
            float k30 = key_s[(rb + 8) * FSTR + colA + 8];
            float k31 = key_s[(rb + 9) * FSTR + colA + 8];
            u32 ah[4], al[4];
            ah[0] = split_pair(k00, k01, al[0]);
            ah[1] = split_pair(k10, k11, al[1]);
            ah[2] = split_pair(k20, k21, al[2]);
            ah[3] = split_pair(k30, k31, al[3]);
#pragma unroll
            for (int j = 0; j < 8; j++) {
                uint4 B = qf_s[(kt * NT2P + nts + j) * 32 + lane];
                mma_bf16(D2[j], ah, B.x, B.y);
                mma_bf16(D2[j], al, B.x, B.y);
                mma_bf16(D2[j], ah, B.z, B.w);
            }
        }

        // ---- stores: c0:(px,n0) c1:(px,n0+1) c2:(px+8,n0) c3:(px+8,n0+1) ----
#pragma unroll
        for (int j = 0; j < 8; j++) {
            int n0 = (nts + j) * 8 + 2 * t;
            float* o0 = outb + (size_t)n0 * HW + colA;
            if (n0 < N_PER)     { o0[0]  = D2[j][0]; o0[8]      = D2[j][2]; }
            if (n0 + 1 < N_PER) { o0[HW] = D2[j][1]; o0[HW + 8] = D2[j][3]; }
        }
    }
}

// ---------------------------------------------------------------------------
extern "C" void kernel_launch(void* const* d_in, const int* in_sizes, int n_in,
                              void* d_out, int out_size) {
    const float* in_feats = (const float*)d_in[0];   // [1200,256]
    const float* feat_map = (const float*)d_in[1];   // [4,256,160,160]
    const float* qry_w    = (const float*)d_in[2];   // [32,256]
    const float* qry_b    = (const float*)d_in[3];   // [32]
    const float* key_w    = (const float*)d_in[4];   // [32,256]
    const float* key_b    = (const float*)d_in[5];   // [32]
    float* out = (float*)d_out;                      // [1200,160,160]

    cudaFuncSetAttribute(seg_mma, cudaFuncAttributeMaxDynamicSharedMemorySize, SM_TOTAL);

    qproj_kernel<<<150, 256>>>(in_feats, qry_w, qry_b);
    pack_kernel<<<(16 * 4 * 32 + BATCH * 2 * NT2P * 32 + 255) / 256, 256>>>(key_w);
    dim3 grid(HW / 128, BATCH);                      // (200, 4)
    seg_mma<<<grid, THREADS, SM_TOTAL>>>(feat_map, key_b, out);
}

// round 7
// speedup vs baseline: 2.6825x; 1.2210x over previous
#include <cuda_runtime.h>
#include <cstdint>

// Fixed problem shapes
#define BATCH   4
#define N_PER   300
#define IN_DIM  256
#define KEY_DIM 32
#define HW      25600       // 160*160
#define THREADS 256
#define NT1     4           // stage1 n-tiles (o: 32/8)
#define NT2P    40          // stage2 n-tiles padded (300->320)
#define FSTR    132         // feat/key smem row stride (floats)

// seg_mma smem byte offsets (dynamic)
#define SM_FEAT0 0
#define SM_FEAT1 16896      // 32*132*4
#define SM_KEY   0          // key tile [32 o][FSTR] overlaps feat buf0
#define SM_QF    33792
#define SM_TOTAL 74752      // 33792 + 40*2*32*16

// qproj smem: w padded [32][65 float4] + x [16][64 float4]
#define QP_W     0
#define QP_X     33280
#define QP_TOTAL 49664

typedef unsigned int u32;

__device__ uint4 g_kwf[16 * 4 * 32];            // [kt16][nt][lane] hi/lo frag
__device__ uint4 g_qf[BATCH * 2 * NT2P * 32];   // [b][kt16][nt][lane]
__device__ float g_q[BATCH * N_PER * KEY_DIM];  // fp32 q projection

// ---------------------------------------------------------------------------
__device__ __forceinline__ u32 packbf(float flo, float fhi) {
    u32 r; asm("cvt.rn.bf16x2.f32 %0, %1, %2;" : "=r"(r) : "f"(fhi), "f"(flo));
    return r;
}
__device__ __forceinline__ u32 split_pair(float f0, float f1, u32& lo) {
    u32 h = packbf(f0, f1);
    float h0 = __uint_as_float(h << 16);
    float h1 = __uint_as_float(h & 0xffff0000u);
    lo = packbf(f0 - h0, f1 - h1);
    return h;
}
__device__ __forceinline__ void mma_bf16(float d[4], const u32 a[4], u32 b0, u32 b1) {
    asm volatile(
        "mma.sync.aligned.m16n8k16.row.col.f32.bf16.bf16.f32 "
        "{%0,%1,%2,%3}, {%4,%5,%6,%7}, {%8,%9}, {%0,%1,%2,%3};"
        : "+f"(d[0]), "+f"(d[1]), "+f"(d[2]), "+f"(d[3])
        : "r"(a[0]), "r"(a[1]), "r"(a[2]), "r"(a[3]), "r"(b0), "r"(b1));
}
__device__ __forceinline__ void cp16(u32 saddr, const void* g) {
    asm volatile("cp.async.cg.shared.global [%0], [%1], 16;" :: "r"(saddr), "l"(g));
}
#define CP_COMMIT()  asm volatile("cp.async.commit_group;" ::: "memory")
#define CP_WAITALL() asm volatile("cp.async.wait_group 0;" ::: "memory")

// ---------------------------------------------------------------------------
// qproj (+ kw fragment pack in first 8 blocks):
// grid 75, 256 thr, block = 16 rows. qry_w/x staged via cp.async; warp = 2 rows.
// ---------------------------------------------------------------------------
__global__ void qproj_kernel(const float* __restrict__ in_feats,
                             const float* __restrict__ qry_w,
                             const float* __restrict__ qry_b,
                             const float* __restrict__ key_w) {
    extern __shared__ char qsm[];
    const float4* w_s4 = (const float4*)(qsm + QP_W);   // stride 65 float4/row
    const float4* x_s4 = (const float4*)(qsm + QP_X);   // stride 64 float4/row
    const u32 sb = (u32)__cvta_generic_to_shared(qsm);

    const int tid = threadIdx.x;
    const int r0  = blockIdx.x * 16;

    // stage qry_w (32 x 64 float4, padded rows) + x (16 x 64 float4)
#pragma unroll
    for (int k = 0; k < 8; k++) {
        int idx = k * 256 + tid;                 // 0..2047
        int o = idx >> 6, i = idx & 63;
        cp16(sb + QP_W + (u32)(o * 65 + i) * 16, qry_w + o * IN_DIM + i * 4);
    }
#pragma unroll
    for (int k = 0; k < 4; k++) {
        int idx = k * 256 + tid;                 // 0..1023
        int row = idx >> 6, i = idx & 63;
        cp16(sb + QP_X + (u32)idx * 16, in_feats + (size_t)(r0 + row) * IN_DIM + i * 4);
    }
    CP_COMMIT();

    // kw fragment pack (independent; first 8 blocks)
    if (blockIdx.x < 8) {
        int idx = blockIdx.x * 256 + tid;        // 0..2047
        int lane = idx & 31, nt = (idx >> 5) & 3, kt = idx >> 7;
        int t = lane & 3, g = lane >> 2;
        int o  = nt * 8 + g;
        int k0 = kt * 16 + 2 * t;
        float w00 = key_w[o * IN_DIM + k0],     w01 = key_w[o * IN_DIM + k0 + 1];
        float w10 = key_w[o * IN_DIM + k0 + 8], w11 = key_w[o * IN_DIM + k0 + 9];
        uint4 v;
        v.x = split_pair(w00, w01, v.z);
        v.y = split_pair(w10, w11, v.w);
        g_kwf[idx] = v;
    }

    CP_WAITALL();
    __syncthreads();

    const int w    = tid >> 5, lane = tid & 31;
    const int rowA = 2 * w, rowB = 2 * w + 1;

    float a00 = 0.f, a01 = 0.f, a10 = 0.f, a11 = 0.f;
#pragma unroll 8
    for (int i = 0; i < 64; i++) {
        float4 wv = w_s4[lane * 65 + i];         // conflict-free LDS.128
        float4 x0 = x_s4[rowA * 64 + i];         // broadcast
        float4 x1 = x_s4[rowB * 64 + i];
        a00 = fmaf(x0.x, wv.x, a00); a01 = fmaf(x0.y, wv.y, a01);
        a00 = fmaf(x0.z, wv.z, a00); a01 = fmaf(x0.w, wv.w, a01);
        a10 = fmaf(x1.x, wv.x, a10); a11 = fmaf(x1.y, wv.y, a11);
        a10 = fmaf(x1.z, wv.z, a10); a11 = fmaf(x1.w, wv.w, a11);
    }
    float bb = qry_b[lane];
    g_q[(r0 + rowA) * KEY_DIM + lane] = a00 + a01 + bb;
    g_q[(r0 + rowB) * KEY_DIM + lane] = a10 + a11 + bb;
}

// ---------------------------------------------------------------------------
// qf pack: q -> hi/lo bf16 fragment-linear layout
// ---------------------------------------------------------------------------
__global__ void pack_qf_kernel() {
    int qi = blockIdx.x * 256 + threadIdx.x;
    if (qi >= BATCH * 2 * NT2P * 32) return;
    int lane = qi & 31;
    int nt   = (qi >> 5) % NT2P;
    int rest = qi / (32 * NT2P);
    int kt = rest & 1, b = rest >> 1;
    int t = lane & 3, g = lane >> 2;
    int n  = nt * 8 + g;
    int o0 = kt * 16 + 2 * t;
    float q00 = 0.f, q01 = 0.f, q10 = 0.f, q11 = 0.f;
    if (n < N_PER) {
        const float* qr = g_q + ((size_t)b * N_PER + n) * KEY_DIM;
        q00 = qr[o0];     q01 = qr[o0 + 1];
        q10 = qr[o0 + 8]; q11 = qr[o0 + 9];
    }
    uint4 v;
    v.x = split_pair(q00, q01, v.z);
    v.y = split_pair(q10, q11, v.w);
    g_qf[qi] = v;
}

// ---------------------------------------------------------------------------
// Fused MMA kernel. Block = 128 px of one image; 8 warps, warp = 16 px rows.
// kw fragments read straight from L2 (g_kwf, shared by all blocks) -> smem
// drops to 74.75KB -> 3 CTAs/SM.
// ---------------------------------------------------------------------------
__global__ void __launch_bounds__(THREADS, 3)
seg_mma(const float* __restrict__ feat_map,
        const float* __restrict__ key_b,
        float* __restrict__ out) {
    extern __shared__ char sm[];
    float* feat_s = (float*)sm;
    float* key_s  = (float*)(sm + SM_KEY);              // [32 o][FSTR px]
    const uint4* qf_s = (const uint4*)(sm + SM_QF);

    const int tid  = threadIdx.x;
    const int w    = tid >> 5, lane = tid & 31;
    const int t    = lane & 3, g = lane >> 2;
    const int b    = blockIdx.y;
    const int p0   = blockIdx.x * 128;
    const int colA = 16 * w + g;

    const u32 sb = (u32)__cvta_generic_to_shared(sm);
    const float* fm = feat_map + (size_t)b * IN_DIM * HW + p0;

    // stage qf(batch) + feat chunk 0
    {
        const uint4* qsrc = g_qf + (size_t)b * 2 * NT2P * 32;
#pragma unroll
        for (int k = 0; k < 10; k++) {
            int i = k * 256 + tid;               // 0..2559
            cp16(sb + SM_QF + (u32)i * 16, qsrc + i);
        }
    }
#pragma unroll
    for (int i = 0; i < 4; i++) {
        int f = i * 256 + tid;
        int row = f >> 5, c4 = f & 31;
        cp16(sb + SM_FEAT0 + (u32)(row * (FSTR * 4) + c4 * 16),
             fm + (size_t)row * HW + c4 * 4);
    }
    CP_COMMIT();

    // ---- Stage 1: K loop, 8 chunks x 32 c, double buffered ----
    float D1[NT1][4];
#pragma unroll
    for (int nt = 0; nt < NT1; nt++)
#pragma unroll
        for (int i = 0; i < 4; i++) D1[nt][i] = 0.f;

    for (int chunk = 0; chunk < 8; chunk++) {
        CP_WAITALL();
        __syncthreads();
        const int buf = chunk & 1;

        if (chunk + 1 < 8) {
            const float* src = fm + (size_t)(chunk + 1) * 32 * HW;
            const u32 dstb = sb + (buf ^ 1) * SM_FEAT1;
#pragma unroll
            for (int i = 0; i < 4; i++) {
                int f = i * 256 + tid;
                int row = f >> 5, c4 = f & 31;
                cp16(dstb + (u32)(row * (FSTR * 4) + c4 * 16),
                     src + (size_t)row * HW + c4 * 4);
            }
            CP_COMMIT();
        }

        const float* fb = feat_s + buf * (SM_FEAT1 / 4);
#pragma unroll
        for (int ksl = 0; ksl < 2; ksl++) {
            const int kt = chunk * 2 + ksl;
            const int rb = ksl * 16 + 2 * t;
            // prefetch B fragments from L2
            uint4 B0 = __ldg(&g_kwf[(kt * 4 + 0) * 32 + lane]);
            uint4 B1 = __ldg(&g_kwf[(kt * 4 + 1) * 32 + lane]);
            uint4 B2 = __ldg(&g_kwf[(kt * 4 + 2) * 32 + lane]);
            uint4 B3 = __ldg(&g_kwf[(kt * 4 + 3) * 32 + lane]);

            float f00 = fb[(rb)     * FSTR + colA];
            float f01 = fb[(rb + 1) * FSTR + colA];
            float f10 = fb[(rb)     * FSTR + colA + 8];
            float f11 = fb[(rb + 1) * FSTR + colA + 8];
            float f20 = fb[(rb + 8) * FSTR + colA];
            float f21 = fb[(rb + 9) * FSTR + colA];
            float f30 = fb[(rb + 8) * FSTR + colA + 8];
            float f31 = fb[(rb + 9) * FSTR + colA + 8];
            u32 ah[4], al[4];
            ah[0] = split_pair(f00, f01, al[0]);
            ah[1] = split_pair(f10, f11, al[1]);
            ah[2] = split_pair(f20, f21, al[2]);
            ah[3] = split_pair(f30, f31, al[3]);

            mma_bf16(D1[0], ah, B0.x, B0.y); mma_bf16(D1[0], al, B0.x, B0.y);
            mma_bf16(D1[0], ah, B0.z, B0.w);
            mma_bf16(D1[1], ah, B1.x, B1.y); mma_bf16(D1[1], al, B1.x, B1.y);
            mma_bf16(D1[1], ah, B1.z, B1.w);
            mma_bf16(D1[2], ah, B2.x, B2.y); mma_bf16(D1[2], al, B2.x, B2.y);
            mma_bf16(D1[2], ah, B2.z, B2.w);
            mma_bf16(D1[3], ah, B3.x, B3.y); mma_bf16(D1[3], al, B3.x, B3.y);
            mma_bf16(D1[3], ah, B3.z, B3.w);
        }
    }

    __syncthreads();      // all feat reads done before key_s overwrites buf0
#pragma unroll
    for (int nt = 0; nt < NT1; nt++)
#pragma unroll
        for (int i = 0; i < 4; i++) {
            int o  = nt * 8 + 2 * t + (i & 1);
            int px = colA + ((i & 2) ? 8 : 0);
            key_s[o * FSTR + px] = D1[nt][i] + key_b[o];
        }
    __syncthreads();

    // ---- Stage 2: 5 chunks of 8 n-tiles ----
    float* outb = out + (size_t)b * N_PER * HW + p0;

    for (int c5 = 0; c5 < 5; c5++) {
        const int nts = c5 * 8;
        float D2[8][4];
#pragma unroll
        for (int j = 0; j < 8; j++)
#pragma unroll
            for (int i = 0; i < 4; i++) D2[j][i] = 0.f;

#pragma unroll
        for (int kt = 0; kt < 2; kt++) {
            const int rb = kt * 16 + 2 * t;
            float k00 = key_s[(rb)     * FSTR + colA];
            float k01 = key_s[(rb + 1) * FSTR + colA];
            float k10 = key_s[(rb)     * FSTR + colA + 8];
            float k11 = key_s[(rb + 1) * FSTR + colA + 8];
            float k20 = key_s[(rb + 8) * FSTR + colA];
            float k21 = key_s[(rb + 9) * FSTR + colA];
            float k30 = key_s[(rb + 8) * FSTR + colA + 8];
            float k31 = key_s[(rb + 9) * FSTR + colA + 8];
            u32 ah[4], al[4];
            ah[0] = split_pair(k00, k01, al[0]);
            ah[1] = split_pair(k10, k11, al[1]);
            ah[2] = split_pair(k20, k21, al[2]);
            ah[3] = split_pair(k30, k31, al[3]);
#pragma unroll
            for (int j = 0; j < 8; j++) {
                uint4 B = qf_s[(kt * NT2P + nts + j) * 32 + lane];
                mma_bf16(D2[j], ah, B.x, B.y);
                mma_bf16(D2[j], al, B.x, B.y);
                mma_bf16(D2[j], ah, B.z, B.w);
            }
        }

#pragma unroll
        for (int j = 0; j < 8; j++) {
            int n0 = (nts + j) * 8 + 2 * t;
            float* o0 = outb + (size_t)n0 * HW + colA;
            if (n0 < N_PER)     { o0[0]  = D2[j][0]; o0[8]      = D2[j][2]; }
            if (n0 + 1 < N_PER) { o0[HW] = D2[j][1]; o0[HW + 8] = D2[j][3]; }
        }
    }
}

// ---------------------------------------------------------------------------
extern "C" void kernel_launch(void* const* d_in, const int* in_sizes, int n_in,
                              void* d_out, int out_size) {
    const float* in_feats = (const float*)d_in[0];   // [1200,256]
    const float* feat_map = (const float*)d_in[1];   // [4,256,160,160]
    const float* qry_w    = (const float*)d_in[2];   // [32,256]
    const float* qry_b    = (const float*)d_in[3];   // [32]
    const float* key_w    = (const float*)d_in[4];   // [32,256]
    const float* key_b    = (const float*)d_in[5];   // [32]
    float* out = (float*)d_out;                      // [1200,160,160]

    cudaFuncSetAttribute(qproj_kernel, cudaFuncAttributeMaxDynamicSharedMemorySize, QP_TOTAL);
    cudaFuncSetAttribute(seg_mma, cudaFuncAttributeMaxDynamicSharedMemorySize, SM_TOTAL);

    qproj_kernel<<<75, 256, QP_TOTAL>>>(in_feats, qry_w, qry_b, key_w);
    pack_qf_kernel<<<(BATCH * 2 * NT2P * 32 + 255) / 256, 256>>>();
    dim3 grid(HW / 128, BATCH);                      // (200, 4)
    seg_mma<<<grid, THREADS, SM_TOTAL>>>(feat_map, key_b, out);
}

// round 8
// speedup vs baseline: 2.9405x; 1.0962x over previous
#include <cuda_runtime.h>
#include <cstdint>

// Fixed problem shapes
#define BATCH   4
#define N_PER   300
#define IN_DIM  256
#define KEY_DIM 32
#define HW      25600       // 160*160
#define NT2P    40          // stage2 n-tiles padded (300->320)
#define FSTR    132         // feat/key smem row stride (floats)

// seg_mma smem byte offsets (dynamic)
#define SM_FEAT0 0
#define SM_FEAT1 16896      // 32*132*4
#define SM_KEY   0          // key tile [32 o][FSTR] overlaps feat buf0
#define SM_QF    33792
#define SM_TOTAL 74752      // 33792 + 40*2*32*16

// qproj smem: w [32][65 float4] + x [8][64 float4] + q [8][32] f32
#define QP_W     0
#define QP_X     33280
#define QP_Q     41472
#define QP_TOTAL 42496

typedef unsigned int u32;

__device__ uint4 g_kwf[16 * 4 * 32];            // [kt16][nt][lane] hi/lo frag
__device__ uint4 g_qf[BATCH * 2 * NT2P * 32];   // [b][kt16][nt][lane] (.bss zero)

// ---------------------------------------------------------------------------
__device__ __forceinline__ u32 packbf(float flo, float fhi) {
    u32 r; asm("cvt.rn.bf16x2.f32 %0, %1, %2;" : "=r"(r) : "f"(fhi), "f"(flo));
    return r;
}
__device__ __forceinline__ u32 split_pair(float f0, float f1, u32& lo) {
    u32 h = packbf(f0, f1);
    float h0 = __uint_as_float(h << 16);
    float h1 = __uint_as_float(h & 0xffff0000u);
    lo = packbf(f0 - h0, f1 - h1);
    return h;
}
__device__ __forceinline__ void mma_bf16(float d[4], const u32 a[4], u32 b0, u32 b1) {
    asm volatile(
        "mma.sync.aligned.m16n8k16.row.col.f32.bf16.bf16.f32 "
        "{%0,%1,%2,%3}, {%4,%5,%6,%7}, {%8,%9}, {%0,%1,%2,%3};"
        : "+f"(d[0]), "+f"(d[1]), "+f"(d[2]), "+f"(d[3])
        : "r"(a[0]), "r"(a[1]), "r"(a[2]), "r"(a[3]), "r"(b0), "r"(b1));
}
__device__ __forceinline__ void cp16(u32 saddr, const void* g) {
    asm volatile("cp.async.cg.shared.global [%0], [%1], 16;" :: "r"(saddr), "l"(g));
}
#define CP_COMMIT()  asm volatile("cp.async.commit_group;" ::: "memory")
#define CP_WAITALL() asm volatile("cp.async.wait_group 0;" ::: "memory")

// ---------------------------------------------------------------------------
// qproj + fragment pack, fused. grid (38, 4), 256 thr.
// Block = 8 rows (one n-tile) of image b; warp = 1 row, lane = o.
// Writes g_qf fragments directly. First 8 blocks of b=0 also pack g_kwf.
// ---------------------------------------------------------------------------
__global__ void qproj_kernel(const float* __restrict__ in_feats,
                             const float* __restrict__ qry_w,
                             const float* __restrict__ qry_b,
                             const float* __restrict__ key_w) {
    extern __shared__ char qsm[];
    const float4* w_s4 = (const float4*)(qsm + QP_W);   // stride 65 float4/row
    const float4* x_s4 = (const float4*)(qsm + QP_X);   // stride 64 float4/row
    float*        q_s  = (float*)(qsm + QP_Q);          // [8][32]
    const u32 sb = (u32)__cvta_generic_to_shared(qsm);

    const int tid = threadIdx.x;
    const int b   = blockIdx.y;
    const int nt  = blockIdx.x;                 // n-tile (8 rows)
    const int n0  = nt * 8;

    // stage qry_w (32 x 64 float4, padded rows)
#pragma unroll
    for (int k = 0; k < 8; k++) {
        int idx = k * 256 + tid;
        int o = idx >> 6, i = idx & 63;
        cp16(sb + QP_W + (u32)(o * 65 + i) * 16, qry_w + o * IN_DIM + i * 4);
    }
    // stage x rows (8 x 64 float4), clamp n>=300 to row 299 (compute zeroed later)
#pragma unroll
    for (int k = 0; k < 2; k++) {
        int idx = k * 256 + tid;
        int row = idx >> 6, i = idx & 63;
        int n = n0 + row; if (n >= N_PER) n = N_PER - 1;
        cp16(sb + QP_X + (u32)idx * 16,
             in_feats + ((size_t)b * N_PER + n) * IN_DIM + i * 4);
    }
    CP_COMMIT();

    // kw fragment pack (first 8 blocks of b=0)
    if (b == 0 && nt < 8) {
        int idx = nt * 256 + tid;               // 0..2047
        int lane = idx & 31, nt1 = (idx >> 5) & 3, kt = idx >> 7;
        int t = lane & 3, g = lane >> 2;
        int o  = nt1 * 8 + g;
        int k0 = kt * 16 + 2 * t;
        float w00 = key_w[o * IN_DIM + k0],     w01 = key_w[o * IN_DIM + k0 + 1];
        float w10 = key_w[o * IN_DIM + k0 + 8], w11 = key_w[o * IN_DIM + k0 + 9];
        uint4 v;
        v.x = split_pair(w00, w01, v.z);
        v.y = split_pair(w10, w11, v.w);
        g_kwf[idx] = v;
    }

    CP_WAITALL();
    __syncthreads();

    const int w    = tid >> 5, lane = tid & 31;
    const int n    = n0 + w;

    float a0 = 0.f, a1 = 0.f, a2 = 0.f, a3 = 0.f;
#pragma unroll 8
    for (int i = 0; i < 64; i++) {
        float4 wv = w_s4[lane * 65 + i];        // conflict-free LDS.128
        float4 xv = x_s4[w * 64 + i];           // broadcast
        a0 = fmaf(xv.x, wv.x, a0);
        a1 = fmaf(xv.y, wv.y, a1);
        a2 = fmaf(xv.z, wv.z, a2);
        a3 = fmaf(xv.w, wv.w, a3);
    }
    float q = (n < N_PER) ? (a0 + a1) + (a2 + a3) + qry_b[lane] : 0.f;
    q_s[w * 32 + lane] = q;
    __syncthreads();

    // fragment build: 2 warps (kt = 0,1)
    if (tid < 64) {
        int kt = tid >> 5;
        int t = lane & 3, g = lane >> 2;
        const float* qr = q_s + g * 32 + kt * 16 + 2 * t;
        uint4 v;
        v.x = split_pair(qr[0], qr[1], v.z);
        v.y = split_pair(qr[8], qr[9], v.w);
        g_qf[((size_t)(b * 2 + kt) * NT2P + nt) * 32 + lane] = v;
    }
}

// ---------------------------------------------------------------------------
// Fused MMA kernel. Block = 128 px of one image; 4 warps, warp = 32 px
// (two m16 fragments). Every B fragment feeds 2 m-frags.
// ---------------------------------------------------------------------------
__global__ void __launch_bounds__(128, 3)
seg_mma(const float* __restrict__ feat_map,
        const float* __restrict__ key_b,
        float* __restrict__ out) {
    extern __shared__ char sm[];
    float* feat_s = (float*)sm;
    float* key_s  = (float*)(sm + SM_KEY);              // [32 o][FSTR px]
    const uint4* qf_s = (const uint4*)(sm + SM_QF);

    const int tid  = threadIdx.x;
    const int w    = tid >> 5, lane = tid & 31;
    const int t    = lane & 3, g = lane >> 2;
    const int b    = blockIdx.y;
    const int p0   = blockIdx.x * 128;
    const int colA = 32 * w + g;                        // m-frag 0 px col
    // m-frag 1 px col = colA + 16

    const u32 sb = (u32)__cvta_generic_to_shared(sm);
    const float* fm = feat_map + (size_t)b * IN_DIM * HW + p0;

    // stage qf(batch) + feat chunk 0
    {
        const uint4* qsrc = g_qf + (size_t)b * 2 * NT2P * 32;
#pragma unroll
        for (int k = 0; k < 20; k++) {
            int i = k * 128 + tid;              // 0..2559
            cp16(sb + SM_QF + (u32)i * 16, qsrc + i);
        }
    }
#pragma unroll
    for (int i = 0; i < 8; i++) {
        int f = i * 128 + tid;
        int row = f >> 5, c4 = f & 31;
        cp16(sb + SM_FEAT0 + (u32)(row * (FSTR * 4) + c4 * 16),
             fm + (size_t)row * HW + c4 * 4);
    }
    CP_COMMIT();

    // ---- Stage 1: K loop, 8 chunks x 32 c, double buffered ----
    float D1[2][4][4];
#pragma unroll
    for (int m = 0; m < 2; m++)
#pragma unroll
        for (int nt = 0; nt < 4; nt++)
#pragma unroll
            for (int i = 0; i < 4; i++) D1[m][nt][i] = 0.f;

    for (int chunk = 0; chunk < 8; chunk++) {
        CP_WAITALL();
        __syncthreads();
        const int buf = chunk & 1;

        if (chunk + 1 < 8) {
            const float* src = fm + (size_t)(chunk + 1) * 32 * HW;
            const u32 dstb = sb + (buf ^ 1) * SM_FEAT1;
#pragma unroll
            for (int i = 0; i < 8; i++) {
                int f = i * 128 + tid;
                int row = f >> 5, c4 = f & 31;
                cp16(dstb + (u32)(row * (FSTR * 4) + c4 * 16),
                     src + (size_t)row * HW + c4 * 4);
            }
            CP_COMMIT();
        }

        const float* fb = feat_s + buf * (SM_FEAT1 / 4);
#pragma unroll
        for (int ksl = 0; ksl < 2; ksl++) {
            const int kt = chunk * 2 + ksl;
            const int rb = ksl * 16 + 2 * t;
            uint4 B0 = __ldg(&g_kwf[(kt * 4 + 0) * 32 + lane]);
            uint4 B1 = __ldg(&g_kwf[(kt * 4 + 1) * 32 + lane]);
            uint4 B2 = __ldg(&g_kwf[(kt * 4 + 2) * 32 + lane]);
            uint4 B3 = __ldg(&g_kwf[(kt * 4 + 3) * 32 + lane]);

            u32 ah[2][4], al[2][4];
#pragma unroll
            for (int m = 0; m < 2; m++) {
                int c0 = colA + m * 16;
                float f00 = fb[(rb)     * FSTR + c0];
                float f01 = fb[(rb + 1) * FSTR + c0];
                float f10 = fb[(rb)     * FSTR + c0 + 8];
                float f11 = fb[(rb + 1) * FSTR + c0 + 8];
                float f20 = fb[(rb + 8) * FSTR + c0];
                float f21 = fb[(rb + 9) * FSTR + c0];
                float f30 = fb[(rb + 8) * FSTR + c0 + 8];
                float f31 = fb[(rb + 9) * FSTR + c0 + 8];
                ah[m][0] = split_pair(f00, f01, al[m][0]);
                ah[m][1] = split_pair(f10, f11, al[m][1]);
                ah[m][2] = split_pair(f20, f21, al[m][2]);
                ah[m][3] = split_pair(f30, f31, al[m][3]);
            }
#pragma unroll
            for (int m = 0; m < 2; m++) {
                mma_bf16(D1[m][0], ah[m], B0.x, B0.y);
                mma_bf16(D1[m][0], al[m], B0.x, B0.y);
                mma_bf16(D1[m][0], ah[m], B0.z, B0.w);
                mma_bf16(D1[m][1], ah[m], B1.x, B1.y);
                mma_bf16(D1[m][1], al[m], B1.x, B1.y);
                mma_bf16(D1[m][1], ah[m], B1.z, B1.w);
                mma_bf16(D1[m][2], ah[m], B2.x, B2.y);
                mma_bf16(D1[m][2], al[m], B2.x, B2.y);
                mma_bf16(D1[m][2], ah[m], B2.z, B2.w);
                mma_bf16(D1[m][3], ah[m], B3.x, B3.y);
                mma_bf16(D1[m][3], al[m], B3.x, B3.y);
                mma_bf16(D1[m][3], ah[m], B3.z, B3.w);
            }
        }
    }

    __syncthreads();      // all feat reads done before key_s overwrites buf0
#pragma unroll
    for (int m = 0; m < 2; m++)
#pragma unroll
        for (int nt = 0; nt < 4; nt++)
#pragma unroll
            for (int i = 0; i < 4; i++) {
                int o  = nt * 8 + 2 * t + (i & 1);
                int px = colA + m * 16 + ((i & 2) ? 8 : 0);
                key_s[o * FSTR + px] = D1[m][nt][i] + key_b[o];
            }
    __syncthreads();

    // ---- Stage 2: 5 chunks of 8 n-tiles, 2 m-frags ----
    float* outb = out + (size_t)b * N_PER * HW + p0;

    for (int c5 = 0; c5 < 5; c5++) {
        const int nts = c5 * 8;
        float D2[2][8][4];
#pragma unroll
        for (int m = 0; m < 2; m++)
#pragma unroll
            for (int j = 0; j < 8; j++)
#pragma unroll
                for (int i = 0; i < 4; i++) D2[m][j][i] = 0.f;

#pragma unroll
        for (int kt = 0; kt < 2; kt++) {
            const int rb = kt * 16 + 2 * t;
            u32 ah[2][4], al[2][4];
#pragma unroll
            for (int m = 0; m < 2; m++) {
                int c0 = colA + m * 16;
                float k00 = key_s[(rb)     * FSTR + c0];
                float k01 = key_s[(rb + 1) * FSTR + c0];
                float k10 = key_s[(rb)     * FSTR + c0 + 8];
                float k11 = key_s[(rb + 1) * FSTR + c0 + 8];
                float k20 = key_s[(rb + 8) * FSTR + c0];
                float k21 = key_s[(rb + 9) * FSTR + c0];
                float k30 = key_s[(rb + 8) * FSTR + c0 + 8];
                float k31 = key_s[(rb + 9) * FSTR + c0 + 8];
                ah[m][0] = split_pair(k00, k01, al[m][0]);
                ah[m][1] = split_pair(k10, k11, al[m][1]);
                ah[m][2] = split_pair(k20, k21, al[m][2]);
                ah[m][3] = split_pair(k30, k31, al[m][3]);
            }
#pragma unroll
            for (int j = 0; j < 8; j++) {
                uint4 B = qf_s[(kt * NT2P + nts + j) * 32 + lane];
#pragma unroll
                for (int m = 0; m < 2; m++) {
                    mma_bf16(D2[m][j], ah[m], B.x, B.y);
                    mma_bf16(D2[m][j], al[m], B.x, B.y);
                    mma_bf16(D2[m][j], ah[m], B.z, B.w);
                }
            }
        }

#pragma unroll
        for (int j = 0; j < 8; j++) {
            int n0 = (nts + j) * 8 + 2 * t;
            float* o0 = outb + (size_t)n0 * HW + colA;
            if (n0 < N_PER) {
                o0[0]  = D2[0][j][0]; o0[8]  = D2[0][j][2];
                o0[16] = D2[1][j][0]; o0[24] = D2[1][j][2];
            }
            if (n0 + 1 < N_PER) {
                o0[HW]      = D2[0][j][1]; o0[HW + 8]  = D2[0][j][3];
                o0[HW + 16] = D2[1][j][1]; o0[HW + 24] = D2[1][j][3];
            }
        }
    }
}

// ---------------------------------------------------------------------------
extern "C" void kernel_launch(void* const* d_in, const int* in_sizes, int n_in,
                              void* d_out, int out_size) {
    const float* in_feats = (const float*)d_in[0];   // [1200,256]
    const float* feat_map = (const float*)d_in[1];   // [4,256,160,160]
    const float* qry_w    = (const float*)d_in[2];   // [32,256]
    const float* qry_b    = (const float*)d_in[3];   // [32]
    const float* key_w    = (const float*)d_in[4];   // [32,256]
    const float* key_b    = (const float*)d_in[5];   // [32]
    float* out = (float*)d_out;                      // [1200,160,160]

    cudaFuncSetAttribute(qproj_kernel, cudaFuncAttributeMaxDynamicSharedMemorySize, QP_TOTAL);
    cudaFuncSetAttribute(seg_mma, cudaFuncAttributeMaxDynamicSharedMemorySize, SM_TOTAL);

    dim3 qgrid(38, BATCH);                           // 152 blocks, 1 wave
    qproj_kernel<<<qgrid, 256, QP_TOTAL>>>(in_feats, qry_w, qry_b, key_w);
    dim3 grid(HW / 128, BATCH);                      // (200, 4)
    seg_mma<<<grid, 128, SM_TOTAL>>>(feat_map, key_b, out);
}

// round 9
// speedup vs baseline: 3.0043x; 1.0217x over previous
#include <cuda_runtime.h>
#include <cstdint>

// Fixed problem shapes
#define BATCH   4
#define N_PER   300
#define IN_DIM  256
#define KEY_DIM 32
#define HW      25600       // 160*160
#define NT2P    40          // stage2 n-tiles padded (300->320)
#define FSTR    132         // feat/key smem row stride (floats)

// seg_mma smem byte offsets (dynamic)
#define SM_FEAT0 0
#define SM_FEAT1 16896      // 32*132*4
#define SM_KEY   0          // key tile [32 o][FSTR] overlaps feat buf0
#define SM_QF    33792
#define SM_TOTAL 74752      // 33792 + 40*2*32*16

// qproj smem: w [32][65 float4] + x [8][64 float4] + q [8][32] f32
#define QP_W     0
#define QP_X     33280
#define QP_Q     41472
#define QP_TOTAL 42496

typedef unsigned int u32;

__device__ uint4 g_kwf[16 * 4 * 32];            // [kt16][nt][lane] hi/lo frag
__device__ uint4 g_qf[BATCH * 2 * NT2P * 32];   // [b][kt16][nt][lane] (.bss zero)

// ---------------------------------------------------------------------------
__device__ __forceinline__ u32 packbf(float flo, float fhi) {
    u32 r; asm("cvt.rn.bf16x2.f32 %0, %1, %2;" : "=r"(r) : "f"(fhi), "f"(flo));
    return r;
}
__device__ __forceinline__ u32 split_pair(float f0, float f1, u32& lo) {
    u32 h = packbf(f0, f1);
    float h0 = __uint_as_float(h << 16);
    float h1 = __uint_as_float(h & 0xffff0000u);
    lo = packbf(f0 - h0, f1 - h1);
    return h;
}
__device__ __forceinline__ void mma_bf16(float d[4], const u32 a[4], u32 b0, u32 b1) {
    asm volatile(
        "mma.sync.aligned.m16n8k16.row.col.f32.bf16.bf16.f32 "
        "{%0,%1,%2,%3}, {%4,%5,%6,%7}, {%8,%9}, {%0,%1,%2,%3};"
        : "+f"(d[0]), "+f"(d[1]), "+f"(d[2]), "+f"(d[3])
        : "r"(a[0]), "r"(a[1]), "r"(a[2]), "r"(a[3]), "r"(b0), "r"(b1));
}
__device__ __forceinline__ void cp16(u32 saddr, const void* g) {
    asm volatile("cp.async.cg.shared.global [%0], [%1], 16;" :: "r"(saddr), "l"(g));
}
#define CP_COMMIT()  asm volatile("cp.async.commit_group;" ::: "memory")
#define CP_WAITALL() asm volatile("cp.async.wait_group 0;" ::: "memory")

// ---------------------------------------------------------------------------
// K0: kw fragment pack (independent of q). 8 blocks x 256.
// ---------------------------------------------------------------------------
__global__ void kwpack_kernel(const float* __restrict__ key_w) {
    int idx = blockIdx.x * 256 + threadIdx.x;   // 0..2047
    int lane = idx & 31, nt1 = (idx >> 5) & 3, kt = idx >> 7;
    int t = lane & 3, g = lane >> 2;
    int o  = nt1 * 8 + g;
    int k0 = kt * 16 + 2 * t;
    float w00 = key_w[o * IN_DIM + k0],     w01 = key_w[o * IN_DIM + k0 + 1];
    float w10 = key_w[o * IN_DIM + k0 + 8], w11 = key_w[o * IN_DIM + k0 + 9];
    uint4 v;
    v.x = split_pair(w00, w01, v.z);
    v.y = split_pair(w10, w11, v.w);
    g_kwf[idx] = v;
}

// ---------------------------------------------------------------------------
// qproj + q fragment pack. grid (38, 4), 256 thr, block = 8 rows.
// Triggers PDL immediately so seg_mma can start stage-1 concurrently.
// ---------------------------------------------------------------------------
__global__ void qproj_kernel(const float* __restrict__ in_feats,
                             const float* __restrict__ qry_w,
                             const float* __restrict__ qry_b) {
    cudaTriggerProgrammaticLaunchCompletion();

    extern __shared__ char qsm[];
    const float4* w_s4 = (const float4*)(qsm + QP_W);   // stride 65 float4/row
    const float4* x_s4 = (const float4*)(qsm + QP_X);   // stride 64 float4/row
    float*        q_s  = (float*)(qsm + QP_Q);          // [8][32]
    const u32 sb = (u32)__cvta_generic_to_shared(qsm);

    const int tid = threadIdx.x;
    const int b   = blockIdx.y;
    const int nt  = blockIdx.x;                 // n-tile (8 rows)
    const int n0  = nt * 8;

#pragma unroll
    for (int k = 0; k < 8; k++) {
        int idx = k * 256 + tid;
        int o = idx >> 6, i = idx & 63;
        cp16(sb + QP_W + (u32)(o * 65 + i) * 16, qry_w + o * IN_DIM + i * 4);
    }
#pragma unroll
    for (int k = 0; k < 2; k++) {
        int idx = k * 256 + tid;
        int row = idx >> 6, i = idx & 63;
        int n = n0 + row; if (n >= N_PER) n = N_PER - 1;
        cp16(sb + QP_X + (u32)idx * 16,
             in_feats + ((size_t)b * N_PER + n) * IN_DIM + i * 4);
    }
    CP_COMMIT();
    CP_WAITALL();
    __syncthreads();

    const int w    = tid >> 5, lane = tid & 31;
    const int n    = n0 + w;

    float a0 = 0.f, a1 = 0.f, a2 = 0.f, a3 = 0.f;
#pragma unroll 8
    for (int i = 0; i < 64; i++) {
        float4 wv = w_s4[lane * 65 + i];        // conflict-free LDS.128
        float4 xv = x_s4[w * 64 + i];           // broadcast
        a0 = fmaf(xv.x, wv.x, a0);
        a1 = fmaf(xv.y, wv.y, a1);
        a2 = fmaf(xv.z, wv.z, a2);
        a3 = fmaf(xv.w, wv.w, a3);
    }
    float q = (n < N_PER) ? (a0 + a1) + (a2 + a3) + qry_b[lane] : 0.f;
    q_s[w * 32 + lane] = q;
    __syncthreads();

    if (tid < 64) {
        int kt = tid >> 5;
        int t = lane & 3, g = lane >> 2;
        const float* qr = q_s + g * 32 + kt * 16 + 2 * t;
        uint4 v;
        v.x = split_pair(qr[0], qr[1], v.z);
        v.y = split_pair(qr[8], qr[9], v.w);
        g_qf[((size_t)(b * 2 + kt) * NT2P + nt) * 32 + lane] = v;
    }
}

// ---------------------------------------------------------------------------
// Stage-2 chunk: JC n-tiles, key fragments hoisted (kh/kl), qf from smem.
// ---------------------------------------------------------------------------
template<int JC>
__device__ __forceinline__ void stage2_chunk(
    int nts, const uint4* qf_s, float* outb,
    const u32 kh[2][2][4], const u32 kl[2][2][4],
    int lane, int t, int colA)
{
    float D2[2][JC][4];
#pragma unroll
    for (int m = 0; m < 2; m++)
#pragma unroll
        for (int j = 0; j < JC; j++)
#pragma unroll
            for (int i = 0; i < 4; i++) D2[m][j][i] = 0.f;

#pragma unroll
    for (int kt = 0; kt < 2; kt++) {
#pragma unroll
        for (int j = 0; j < JC; j++) {
            uint4 B = qf_s[(kt * NT2P + nts + j) * 32 + lane];
#pragma unroll
            for (int m = 0; m < 2; m++) {
                mma_bf16(D2[m][j], kh[kt][m], B.x, B.y);
                mma_bf16(D2[m][j], kl[kt][m], B.x, B.y);
                mma_bf16(D2[m][j], kh[kt][m], B.z, B.w);
            }
        }
    }

#pragma unroll
    for (int j = 0; j < JC; j++) {
        int n0 = (nts + j) * 8 + 2 * t;
        float* o0 = outb + (size_t)n0 * HW + colA;
        if (n0 < N_PER) {
            o0[0]  = D2[0][j][0]; o0[8]  = D2[0][j][2];
            o0[16] = D2[1][j][0]; o0[24] = D2[1][j][2];
        }
        if (n0 + 1 < N_PER) {
            o0[HW]      = D2[0][j][1]; o0[HW + 8]  = D2[0][j][3];
            o0[HW + 16] = D2[1][j][1]; o0[HW + 24] = D2[1][j][3];
        }
    }
}

// ---------------------------------------------------------------------------
// Fused MMA kernel. Block = 128 px; 4 warps, warp = 32 px (2 m16 frags).
// Launched with PDL: stage-1 runs concurrently with qproj; GDS before qf use.
// ---------------------------------------------------------------------------
__global__ void __launch_bounds__(128, 3)
seg_mma(const float* __restrict__ feat_map,
        const float* __restrict__ key_b,
        float* __restrict__ out) {
    extern __shared__ char sm[];
    float* feat_s = (float*)sm;
    float* key_s  = (float*)(sm + SM_KEY);              // [32 o][FSTR px]
    const uint4* qf_s = (const uint4*)(sm + SM_QF);

    const int tid  = threadIdx.x;
    const int w    = tid >> 5, lane = tid & 31;
    const int t    = lane & 3, g = lane >> 2;
    const int b    = blockIdx.y;
    const int p0   = blockIdx.x * 128;
    const int colA = 32 * w + g;

    const u32 sb = (u32)__cvta_generic_to_shared(sm);
    const float* fm = feat_map + (size_t)b * IN_DIM * HW + p0;

    // feat chunk 0
#pragma unroll
    for (int i = 0; i < 8; i++) {
        int f = i * 128 + tid;
        int row = f >> 5, c4 = f & 31;
        cp16(sb + SM_FEAT0 + (u32)(row * (FSTR * 4) + c4 * 16),
             fm + (size_t)row * HW + c4 * 4);
    }
    CP_COMMIT();

    // ---- Stage 1: K loop, 8 chunks x 32 c, double buffered ----
    float D1[2][4][4];
#pragma unroll
    for (int m = 0; m < 2; m++)
#pragma unroll
        for (int nt = 0; nt < 4; nt++)
#pragma unroll
            for (int i = 0; i < 4; i++) D1[m][nt][i] = 0.f;

    for (int chunk = 0; chunk < 8; chunk++) {
        CP_WAITALL();
        __syncthreads();
        const int buf = chunk & 1;

        if (chunk + 1 < 8) {
            const float* src = fm + (size_t)(chunk + 1) * 32 * HW;
            const u32 dstb = sb + (buf ^ 1) * SM_FEAT1;
#pragma unroll
            for (int i = 0; i < 8; i++) {
                int f = i * 128 + tid;
                int row = f >> 5, c4 = f & 31;
                cp16(dstb + (u32)(row * (FSTR * 4) + c4 * 16),
                     src + (size_t)row * HW + c4 * 4);
            }
            CP_COMMIT();
        }

        const float* fb = feat_s + buf * (SM_FEAT1 / 4);
#pragma unroll
        for (int ksl = 0; ksl < 2; ksl++) {
            const int kt = chunk * 2 + ksl;
            const int rb = ksl * 16 + 2 * t;
            uint4 B0 = __ldg(&g_kwf[(kt * 4 + 0) * 32 + lane]);
            uint4 B1 = __ldg(&g_kwf[(kt * 4 + 1) * 32 + lane]);
            uint4 B2 = __ldg(&g_kwf[(kt * 4 + 2) * 32 + lane]);
            uint4 B3 = __ldg(&g_kwf[(kt * 4 + 3) * 32 + lane]);

            u32 ah[2][4], al[2][4];
#pragma unroll
            for (int m = 0; m < 2; m++) {
                int c0 = colA + m * 16;
                float f00 = fb[(rb)     * FSTR + c0];
                float f01 = fb[(rb + 1) * FSTR + c0];
                float f10 = fb[(rb)     * FSTR + c0 + 8];
                float f11 = fb[(rb + 1) * FSTR + c0 + 8];
                float f20 = fb[(rb + 8) * FSTR + c0];
                float f21 = fb[(rb + 9) * FSTR + c0];
                float f30 = fb[(rb + 8) * FSTR + c0 + 8];
                float f31 = fb[(rb + 9) * FSTR + c0 + 8];
                ah[m][0] = split_pair(f00, f01, al[m][0]);
                ah[m][1] = split_pair(f10, f11, al[m][1]);
                ah[m][2] = split_pair(f20, f21, al[m][2]);
                ah[m][3] = split_pair(f30, f31, al[m][3]);
            }
#pragma unroll
            for (int m = 0; m < 2; m++) {
                mma_bf16(D1[m][0], ah[m], B0.x, B0.y);
                mma_bf16(D1[m][0], al[m], B0.x, B0.y);
                mma_bf16(D1[m][0], ah[m], B0.z, B0.w);
                mma_bf16(D1[m][1], ah[m], B1.x, B1.y);
                mma_bf16(D1[m][1], al[m], B1.x, B1.y);
                mma_bf16(D1[m][1], ah[m], B1.z, B1.w);
                mma_bf16(D1[m][2], ah[m], B2.x, B2.y);
                mma_bf16(D1[m][2], al[m], B2.x, B2.y);
                mma_bf16(D1[m][2], ah[m], B2.z, B2.w);
                mma_bf16(D1[m][3], ah[m], B3.x, B3.y);
                mma_bf16(D1[m][3], al[m], B3.x, B3.y);
                mma_bf16(D1[m][3], ah[m], B3.z, B3.w);
            }
        }
    }

    __syncthreads();      // all feat reads done before key_s overwrites buf0
#pragma unroll
    for (int m = 0; m < 2; m++)
#pragma unroll
        for (int nt = 0; nt < 4; nt++)
#pragma unroll
            for (int i = 0; i < 4; i++) {
                int o  = nt * 8 + 2 * t + (i & 1);
                int px = colA + m * 16 + ((i & 2) ? 8 : 0);
                key_s[o * FSTR + px] = D1[m][nt][i] + key_b[o];
            }

    // ---- wait for qproj (PDL), then stage qf ----
    cudaGridDependencySynchronize();
    {
        const uint4* qsrc = g_qf + (size_t)b * 2 * NT2P * 32;
#pragma unroll
        for (int k = 0; k < 20; k++) {
            int i = k * 128 + tid;              // 0..2559
            cp16(sb + SM_QF + (u32)i * 16, qsrc + i);
        }
    }
    CP_COMMIT();
    CP_WAITALL();
    __syncthreads();                            // key_s + qf_s ready

    // ---- Stage 2: hoist key fragments once, then 4x8 + 1x6 n-tiles ----
    u32 kh[2][2][4], kl[2][2][4];
#pragma unroll
    for (int kt = 0; kt < 2; kt++) {
        const int rb = kt * 16 + 2 * t;
#pragma unroll
        for (int m = 0; m < 2; m++) {
            int c0 = colA + m * 16;
            float k00 = key_s[(rb)     * FSTR + c0];
            float k01 = key_s[(rb + 1) * FSTR + c0];
            float k10 = key_s[(rb)     * FSTR + c0 + 8];
            float k11 = key_s[(rb + 1) * FSTR + c0 + 8];
            float k20 = key_s[(rb + 8) * FSTR + c0];
            float k21 = key_s[(rb + 9) * FSTR + c0];
            float k30 = key_s[(rb + 8) * FSTR + c0 + 8];
            float k31 = key_s[(rb + 9) * FSTR + c0 + 8];
            kh[kt][m][0] = split_pair(k00, k01, kl[kt][m][0]);
            kh[kt][m][1] = split_pair(k10, k11, kl[kt][m][1]);
            kh[kt][m][2] = split_pair(k20, k21, kl[kt][m][2]);
            kh[kt][m][3] = split_pair(k30, k31, kl[kt][m][3]);
        }
    }

    float* outb = out + (size_t)b * N_PER * HW + p0;
#pragma unroll 1
    for (int c5 = 0; c5 < 4; c5++)
        stage2_chunk<8>(c5 * 8, qf_s, outb, kh, kl, lane, t, colA);
    stage2_chunk<6>(32, qf_s, outb, kh, kl, lane, t, colA);
}

// ---------------------------------------------------------------------------
extern "C" void kernel_launch(void* const* d_in, const int* in_sizes, int n_in,
                              void* d_out, int out_size) {
    const float* in_feats = (const float*)d_in[0];   // [1200,256]
    const float* feat_map = (const float*)d_in[1];   // [4,256,160,160]
    const float* qry_w    = (const float*)d_in[2];   // [32,256]
    const float* qry_b    = (const float*)d_in[3];   // [32]
    const float* key_w    = (const float*)d_in[4];   // [32,256]
    const float* key_b    = (const float*)d_in[5];   // [32]
    float* out = (float*)d_out;                      // [1200,160,160]

    cudaFuncSetAttribute(qproj_kernel, cudaFuncAttributeMaxDynamicSharedMemorySize, QP_TOTAL);
    cudaFuncSetAttribute(seg_mma, cudaFuncAttributeMaxDynamicSharedMemorySize, SM_TOTAL);

    // K0: kw fragments (complete before qproj starts -> safe for seg stage-1)
    kwpack_kernel<<<8, 256>>>(key_w);

    // qproj: triggers PDL at entry
    dim3 qgrid(38, BATCH);
    qproj_kernel<<<qgrid, 256, QP_TOTAL>>>(in_feats, qry_w, qry_b);

    // seg: PDL-launch so stage-1 overlaps qproj; GDS guards qf reads
    cudaLaunchConfig_t cfg = {};
    cfg.gridDim  = dim3(HW / 128, BATCH);            // (200, 4)
    cfg.blockDim = dim3(128, 1, 1);
    cfg.dynamicSmemBytes = SM_TOTAL;
    cfg.stream = 0;
    cudaLaunchAttribute attrs[1];
    attrs[0].id = cudaLaunchAttributeProgrammaticStreamSerialization;
    attrs[0].val.programmaticStreamSerializationAllowed = 1;
    cfg.attrs = attrs;
    cfg.numAttrs = 1;
    cudaLaunchKernelEx(&cfg, seg_mma, feat_map, key_b, out);
}